// round 15
// baseline (speedup 1.0000x reference)
#include <cuda_runtime.h>
#include <cuda_bf16.h>
#include <cstdint>

// ---------------------------------------------------------------------------
// Problem constants
// ---------------------------------------------------------------------------
#define HH      128
#define WW      128
#define MM      16
#define CIN     128
#define NC      7
#define HID     256
#define STY     256
#define COL     64
#define HWPIX   (HH * WW)            // 16384
#define S_TOT   (HWPIX * MM)         // 262144
#define KQ1     192                  // padded K for layer 1

#define QMAX    16256.0f             // 127 * 128
#define QDEN    (16256.0f * 16256.0f)

// ---------------------------------------------------------------------------
// Scratch (device globals)
// ---------------------------------------------------------------------------
__device__ int8_t d_xq1[(size_t)S_TOT * KQ1];
__device__ int8_t d_xq2[(size_t)S_TOT * KQ1];
__device__ float  d_xs[S_TOT];
__device__ int8_t d_aq1[(size_t)S_TOT * HID];
__device__ int8_t d_aq2[(size_t)S_TOT * HID];
__device__ float  d_as[S_TOT];
__device__ int8_t d_bq1[(size_t)S_TOT * HID];
__device__ int8_t d_bq2[(size_t)S_TOT * HID];
__device__ float  d_bsc[S_TOT];
__device__ int8_t d_w1q1[HID * KQ1];
__device__ int8_t d_w1q2[HID * KQ1];
__device__ float  d_w1s[HID];
__device__ int8_t d_wmq1[5 * HID * HID];
__device__ int8_t d_wmq2[5 * HID * HID];
__device__ float  d_wms[5 * HID];
__device__ int8_t d_wcq1[COL * HID];
__device__ int8_t d_wcq2[COL * HID];
__device__ float  d_wcs[COL];
// CNN: fp transposed 3x3 weights, runtime-requantized int8 weights, scales
__device__ float  d_wt3f[4 * 9 * HID * HID];     // [conv][tap][O][K] fp32
__device__ int8_t d_cwq1[9 * HID * HID];
__device__ int8_t d_cwq2[9 * HID * HID];
__device__ float  d_cts[HID];
__device__ float  d_camax[7 * HID];
// CNN activations: bf16 hi/lo pairs + int8 quantized planes
__device__ __nv_bfloat16 d_yah[HWPIX * HID];
__device__ __nv_bfloat16 d_yal[HWPIX * HID];
__device__ __nv_bfloat16 d_ybh[HWPIX * HID];
__device__ __nv_bfloat16 d_ybl[HWPIX * HID];
__device__ __nv_bfloat16 d_ych[HWPIX * HID];
__device__ __nv_bfloat16 d_ycl[HWPIX * HID];
__device__ __nv_bfloat16 d_feath[HWPIX * COL];
__device__ __nv_bfloat16 d_featl[HWPIX * COL];
__device__ int8_t d_cq1[HWPIX * HID];
__device__ int8_t d_cq2[HWPIX * HID];
__device__ float d_sig[S_TOT];
__device__ float d_alpha[5 * HID];
__device__ float d_beta[5 * HID];
__device__ float d_zc[4 * HID];

static __device__ __forceinline__ float lrelu(float v) {
    return v > 0.f ? v : 0.2f * v;
}

static __device__ __forceinline__ uint32_t smem_u32(const void* p) {
    uint32_t a;
    asm("{ .reg .u64 t; cvta.to.shared.u64 t, %1; cvt.u32.u64 %0, t; }" : "=r"(a) : "l"(p));
    return a;
}

static __device__ __forceinline__ void cpa16z(uint32_t dst, const void* src, uint32_t sz) {
    asm volatile("cp.async.cg.shared.global [%0], [%1], 16, %2;"
                 :: "r"(dst), "l"(src), "r"(sz));
}

static __device__ __forceinline__ void ldm_x4(uint32_t* r, uint32_t addr) {
    asm volatile("ldmatrix.sync.aligned.m8n8.x4.shared.b16 {%0,%1,%2,%3}, [%4];"
                 : "=r"(r[0]), "=r"(r[1]), "=r"(r[2]), "=r"(r[3]) : "r"(addr));
}

static __device__ __forceinline__ void imma16832(int* d, const uint32_t* a, const uint32_t* b) {
    asm volatile(
        "mma.sync.aligned.m16n8k32.row.col.s32.s8.s8.s32 "
        "{%0,%1,%2,%3}, {%4,%5,%6,%7}, {%8,%9}, {%0,%1,%2,%3};"
        : "+r"(d[0]), "+r"(d[1]), "+r"(d[2]), "+r"(d[3])
        : "r"(a[0]), "r"(a[1]), "r"(a[2]), "r"(a[3]), "r"(b[0]), "r"(b[1]));
}

static __device__ __forceinline__ uint32_t ldm_a_addr(uint32_t base, int lane) {
    return base + (uint32_t)(lane & 15) * 80 + (uint32_t)((lane >> 4) << 4);
}
static __device__ __forceinline__ uint32_t ldm_b_addr(uint32_t base, int lane) {
    const int n = (lane & 7) + ((lane >= 16) ? 8 : 0);
    const int k16 = ((lane >> 3) & 1) << 4;
    return base + (uint32_t)n * 80 + (uint32_t)k16;
}

static __device__ __forceinline__ void quant2(float v, float inv, int& q1, int& q2) {
    float qf = rintf(v * inv);
    int   q  = (int)qf;
    q1 = (int)rintf(qf * (1.f / 128.f));
    q2 = q - (q1 << 7);
}

static __device__ __forceinline__ void amax_atomic(float* addr, float v) {
    atomicMax(reinterpret_cast<int*>(addr), __float_as_int(v));
}

// ---------------------------------------------------------------------------
// Prep kernels
// ---------------------------------------------------------------------------
__global__ void prep_vec(const float* __restrict__ z,
                         const float* __restrict__ wa, const float* __restrict__ ba,
                         const float* __restrict__ wb, const float* __restrict__ bb,
                         const float* __restrict__ wz, const float* __restrict__ bz) {
    int warp = (blockIdx.x * blockDim.x + threadIdx.x) >> 5;
    int lane = threadIdx.x & 31;
    if (warp >= 3584) return;
    const float* row; float bias; float* out;
    if (warp < 1280)      { row = wa + (size_t)warp * STY; bias = ba[warp]; out = d_alpha + warp; }
    else if (warp < 2560) { int i = warp - 1280; row = wb + (size_t)i * STY; bias = bb[i]; out = d_beta + i; }
    else                  { int i = warp - 2560; row = wz + (size_t)i * STY; bias = bz[i]; out = d_zc + i; }
    float acc = 0.f;
    #pragma unroll
    for (int t = 0; t < 8; t++) acc += z[lane + 32 * t] * row[lane + 32 * t];
    #pragma unroll
    for (int off = 16; off; off >>= 1) acc += __shfl_xor_sync(0xFFFFFFFFu, acc, off);
    if (lane == 0) *out = acc + bias;
}

static __device__ __forceinline__ float warp_amax(float a) {
    #pragma unroll
    for (int off = 16; off; off >>= 1) a = fmaxf(a, __shfl_xor_sync(0xFFFFFFFFu, a, off));
    return a;
}

__global__ void prep_xq(const float* __restrict__ x, const float* __restrict__ m) {
    int s = blockIdx.x * 8 + (threadIdx.x >> 5);
    int lane = threadIdx.x & 31;
    if (s >= S_TOT) return;
    float v[6];
    #pragma unroll
    for (int t = 0; t < 6; t++) {
        int c = lane + 32 * t;
        float val = 0.f;
        if (c < CIN)           val = x[(size_t)s * CIN + c];
        else if (c < CIN + NC) val = m[(size_t)s * NC + (c - CIN)];
        v[t] = val;
    }
    float am = 0.f;
    #pragma unroll
    for (int t = 0; t < 6; t++) am = fmaxf(am, fabsf(v[t]));
    am = warp_amax(am);
    if (lane == 0) d_xs[s] = am;
    float inv = QMAX / fmaxf(am, 1e-20f);
    #pragma unroll
    for (int t = 0; t < 6; t++) {
        int c = lane + 32 * t;
        int q1, q2; quant2(v[t], inv, q1, q2);
        d_xq1[(size_t)s * KQ1 + c] = (int8_t)q1;
        d_xq2[(size_t)s * KQ1 + c] = (int8_t)q2;
    }
}

__global__ void prep_w1q(const float* __restrict__ w1, const float* __restrict__ wma) {
    int o = blockIdx.x * 8 + (threadIdx.x >> 5);
    int lane = threadIdx.x & 31;
    if (o >= HID) return;
    float v[6];
    #pragma unroll
    for (int t = 0; t < 6; t++) {
        int c = lane + 32 * t;
        float val = 0.f;
        if (c < CIN)           val = w1[(size_t)o * CIN + c];
        else if (c < CIN + NC) val = wma[(size_t)o * NC + (c - CIN)];
        v[t] = val;
    }
    float am = 0.f;
    #pragma unroll
    for (int t = 0; t < 6; t++) am = fmaxf(am, fabsf(v[t]));
    am = warp_amax(am);
    if (lane == 0) d_w1s[o] = am;
    float inv = QMAX / fmaxf(am, 1e-20f);
    #pragma unroll
    for (int t = 0; t < 6; t++) {
        int c = lane + 32 * t;
        int q1, q2; quant2(v[t], inv, q1, q2);
        d_w1q1[(size_t)o * KQ1 + c] = (int8_t)q1;
        d_w1q2[(size_t)o * KQ1 + c] = (int8_t)q2;
    }
}

__global__ void prep_wmq(const float* __restrict__ mlw) {
    int r = blockIdx.x * 8 + (threadIdx.x >> 5);
    int lane = threadIdx.x & 31;
    if (r >= 5 * HID) return;
    int layer = r >> 8;
    float v[8];
    #pragma unroll
    for (int t = 0; t < 8; t++) {
        int k = lane + 32 * t;
        v[t] = mlw[(size_t)r * HID + k] * d_alpha[layer * HID + k];
    }
    float am = 0.f;
    #pragma unroll
    for (int t = 0; t < 8; t++) am = fmaxf(am, fabsf(v[t]));
    am = warp_amax(am);
    if (lane == 0) d_wms[r] = am;
    float inv = QMAX / fmaxf(am, 1e-20f);
    #pragma unroll
    for (int t = 0; t < 8; t++) {
        int k = lane + 32 * t;
        int q1, q2; quant2(v[t], inv, q1, q2);
        d_wmq1[(size_t)r * HID + k] = (int8_t)q1;
        d_wmq2[(size_t)r * HID + k] = (int8_t)q2;
    }
}

__global__ void prep_wcq(const float* __restrict__ wc) {
    int o = blockIdx.x * 8 + (threadIdx.x >> 5);
    int lane = threadIdx.x & 31;
    if (o >= COL) return;
    float v[8];
    #pragma unroll
    for (int t = 0; t < 8; t++) v[t] = wc[(size_t)o * HID + lane + 32 * t];
    float am = 0.f;
    #pragma unroll
    for (int t = 0; t < 8; t++) am = fmaxf(am, fabsf(v[t]));
    am = warp_amax(am);
    if (lane == 0) d_wcs[o] = am;
    float inv = QMAX / fmaxf(am, 1e-20f);
    #pragma unroll
    for (int t = 0; t < 8; t++) {
        int q1, q2; quant2(v[t], inv, q1, q2);
        d_wcq1[(size_t)o * HID + lane + 32 * t] = (int8_t)q1;
        d_wcq2[(size_t)o * HID + lane + 32 * t] = (int8_t)q2;
    }
}

__global__ void prep_twf(const float* __restrict__ w, float* __restrict__ out) {
    int idx = blockIdx.x * blockDim.x + threadIdx.x;
    if (idx >= 9 * HID * HID) return;
    int tap = idx / (HID * HID);
    int ok  = idx - tap * (HID * HID);
    out[idx] = w[(size_t)ok * 9 + tap];
}

__global__ void reset_amax() {
    int idx = blockIdx.x * blockDim.x + threadIdx.x;
    if (idx < 7 * HID) d_camax[idx] = 0.f;
}

// ---------------------------------------------------------------------------
// Fused activation-quant + weight-requant.
// Blocks [0, nq): quantize activations (bf16 pair -> int8 planes).
// Blocks [nq, nq+32): per-out-channel weight requant (fold camax).
// ---------------------------------------------------------------------------
template<int C, int TAPS, int K>
__global__ void qa_wr(const __nv_bfloat16* __restrict__ hi,
                      const __nv_bfloat16* __restrict__ lo,
                      const float* __restrict__ camax,
                      int8_t* __restrict__ q1p, int8_t* __restrict__ q2p,
                      const float* __restrict__ wsrc,
                      int8_t* __restrict__ wq1, int8_t* __restrict__ wq2,
                      float* __restrict__ Ts, int nq) {
    if ((int)blockIdx.x < nq) {
        int idx = blockIdx.x * 256 + threadIdx.x;
        if (idx >= HWPIX * C) return;
        int c = idx & (C - 1);
        float v = __bfloat162float(hi[idx]) + __bfloat162float(lo[idx]);
        float inv = QMAX / fmaxf(camax[c], 1e-20f);
        int q1, q2; quant2(v, inv, q1, q2);
        q1p[idx] = (int8_t)q1;
        q2p[idx] = (int8_t)q2;
    } else {
        int o = (blockIdx.x - nq) * 8 + (threadIdx.x >> 5);
        int lane = threadIdx.x & 31;
        if (o >= HID) return;
        const int E = TAPS * K;
        float am = 0.f;
        for (int e = lane; e < E; e += 32) {
            int tap = e / K, k = e - tap * K;
            float u = wsrc[(size_t)tap * (HID * K) + (size_t)o * K + k] * camax[k];
            am = fmaxf(am, fabsf(u));
        }
        am = warp_amax(am);
        if (lane == 0) Ts[o] = am / QDEN;
        float inv = QMAX / fmaxf(am, 1e-20f);
        for (int e = lane; e < E; e += 32) {
            int tap = e / K, k = e - tap * K;
            size_t idx = (size_t)tap * (HID * K) + (size_t)o * K + k;
            float u = wsrc[idx] * camax[k];
            int q1, q2; quant2(u, inv, q1, q2);
            wq1[idx] = (int8_t)q1;
            wq2[idx] = (int8_t)q2;
        }
    }
}

// ---------------------------------------------------------------------------
// MLP int8 GEMM, B-resident; 2 K-chunks per barrier, 3 rotating A buffers.
// 512 threads; WN=8, WM=2, MI=2; CTA owns MT*MTILES rows.
// ---------------------------------------------------------------------------
template<int NTHR, int MT, int MTILES, int NT, int K, bool LRELU_, bool QOUT>
__global__ void __launch_bounds__(NTHR)
imma_brg(const int8_t* __restrict__ Aq1, const int8_t* __restrict__ Aq2,
         const float* __restrict__ As,
         const int8_t* __restrict__ Bq1, const int8_t* __restrict__ Bq2,
         const float* __restrict__ Bs,
         const float* __restrict__ bias,
         int8_t* __restrict__ Oq1, int8_t* __restrict__ Oq2, float* __restrict__ Os,
         float* __restrict__ Of, int OC) {
    extern __shared__ char smem[];
    constexpr int NCH  = K / 64;
    constexpr int NHALF = (NCH + 1) / 2;
    constexpr int NGI2 = MTILES * NHALF;
    constexpr int BSL  = NT * 80;
    constexpr int ASL  = MT * 80;
    constexpr int CSL  = 2 * ASL;            // one chunk, both planes
    constexpr int ABUF = 2 * CSL;            // one buffer holds 2 chunks
    constexpr int B2OFF = NCH * BSL;
    constexpr int AO   = 2 * NCH * BSL;
    constexpr int SFO  = AO + 3 * ABUF;
    constexpr int NW   = NTHR / 32;
    constexpr int WN   = NT / 32;
    constexpr int WM   = NW / WN;
    constexpr int MI   = MT / (16 * WM);

    const uint32_t sb = smem_u32(smem);
    const int tid = threadIdx.x;
    const int lane = tid & 31, wid = tid >> 5;
    const int wn = wid % WN, wm = wid / WN;
    const int g = lane >> 2, q = lane & 3;
    const int rbase0 = blockIdx.x * (MT * MTILES);

    // ---- B: all chunks, both planes, once ----
    for (int idx = tid; idx < NCH * NT * 4; idx += NTHR) {
        const int ch = idx / (NT * 4);
        const int rem = idx - ch * (NT * 4);
        const int row = rem >> 2, cc = rem & 3;
        const size_t go = (size_t)row * K + ch * 64 + cc * 16;
        const uint32_t d = sb + ch * BSL + row * 80 + cc * 16;
        cpa16z(d,         Bq1 + go, 16);
        cpa16z(d + B2OFF, Bq2 + go, 16);
    }
    auto load_A2 = [&](int bufi, int gi2) {
        const int mt = gi2 / NHALF, h = gi2 - mt * NHALF;
        const int ncc = (2 * h + 2 <= NCH) ? 2 : 1;
        for (int idx = tid; idx < ncc * MT * 4; idx += NTHR) {
            const int ci = idx / (MT * 4);
            const int rem = idx - ci * (MT * 4);
            const int row = rem >> 2, cc4 = rem & 3;
            const int c = 2 * h + ci;
            const size_t go = (size_t)(rbase0 + mt * MT + row) * K + c * 64 + cc4 * 16;
            const uint32_t d = sb + AO + bufi * ABUF + ci * CSL + row * 80 + cc4 * 16;
            cpa16z(d,       Aq1 + go, 16);
            cpa16z(d + ASL, Aq2 + go, 16);
        }
    };
    load_A2(0, 0);
    asm volatile("cp.async.commit_group;" ::: "memory");

    int acc1[MI][4][4], acc2[MI][4][4];
    #pragma unroll
    for (int i = 0; i < MI; i++)
        #pragma unroll
        for (int j = 0; j < 4; j++)
            #pragma unroll
            for (int r = 0; r < 4; r++) { acc1[i][j][r] = 0; acc2[i][j][r] = 0; }

    float* sf = reinterpret_cast<float*>(smem + SFO);
    int buf = 0, nbuf = 1;

    for (int gi2 = 0; gi2 < NGI2; gi2++) {
        if (gi2 + 1 < NGI2) {
            load_A2(nbuf, gi2 + 1);
            asm volatile("cp.async.commit_group;" ::: "memory");
            asm volatile("cp.async.wait_group 1;" ::: "memory");
        } else {
            asm volatile("cp.async.wait_group 0;" ::: "memory");
        }
        __syncthreads();
        const int mt = gi2 / NHALF, h = gi2 - mt * NHALF;
        const int ncc = (2 * h + 2 <= NCH) ? 2 : 1;
        for (int ci = 0; ci < ncc; ci++) {
            const int c = 2 * h + ci;
            const uint32_t Ab = sb + AO + buf * ABUF + ci * CSL;
            const uint32_t Bb = sb + c * BSL;
            #pragma unroll
            for (int kk = 0; kk < 2; kk++) {
                const int koff = kk * 32;
                uint32_t a1[MI][4], a2[MI][4];
                #pragma unroll
                for (int i = 0; i < MI; i++) {
                    const uint32_t r0 = ldm_a_addr(Ab + (uint32_t)(wm * MI * 16 + i * 16) * 80 + koff, lane);
                    ldm_x4(a1[i], r0);
                    ldm_x4(a2[i], r0 + ASL);
                }
                uint32_t b1[4][2], b2[4][2];
                #pragma unroll
                for (int jp = 0; jp < 2; jp++) {
                    const uint32_t r0 = ldm_b_addr(Bb + (uint32_t)(wn * 32 + jp * 16) * 80 + koff, lane);
                    uint32_t t[4];
                    ldm_x4(t, r0);
                    b1[2 * jp][0] = t[0]; b1[2 * jp][1] = t[1];
                    b1[2 * jp + 1][0] = t[2]; b1[2 * jp + 1][1] = t[3];
                    ldm_x4(t, r0 + B2OFF);
                    b2[2 * jp][0] = t[0]; b2[2 * jp][1] = t[1];
                    b2[2 * jp + 1][0] = t[2]; b2[2 * jp + 1][1] = t[3];
                }
                #pragma unroll
                for (int i = 0; i < MI; i++)
                    #pragma unroll
                    for (int j = 0; j < 4; j++) {
                        imma16832(acc1[i][j], a1[i], b1[j]);
                        imma16832(acc2[i][j], a1[i], b2[j]);
                        imma16832(acc2[i][j], a2[i], b1[j]);
                    }
            }
        }
        buf = nbuf; nbuf = (nbuf == 2) ? 0 : nbuf + 1;

        if (h == NHALF - 1) {
            // ---- epilogue for m-tile mt ----
            const int rbase = rbase0 + mt * MT;
            if (QOUT) {
                for (int i2 = tid; i2 < MT; i2 += NTHR) sf[i2] = 0.f;
                __syncthreads();
            }
            float sbv[4][2], bv[4][2];
            #pragma unroll
            for (int j = 0; j < 4; j++) {
                const int col0 = wn * 32 + j * 8 + q * 2;
                sbv[j][0] = Bs[col0];     sbv[j][1] = Bs[col0 + 1];
                bv[j][0]  = bias[col0];   bv[j][1]  = bias[col0 + 1];
            }
            #pragma unroll
            for (int i = 0; i < MI; i++) {
                #pragma unroll
                for (int h2 = 0; h2 < 2; h2++) {
                    const int lrow = wm * MI * 16 + i * 16 + g + h2 * 8;
                    const float sa = As[rbase + lrow] * (1.f / QDEN);
                    float rmax = 0.f;
                    #pragma unroll
                    for (int j = 0; j < 4; j++) {
                        float t0 = 16384.f * (float)acc1[i][j][h2 * 2 + 0] + 128.f * (float)acc2[i][j][h2 * 2 + 0];
                        float t1 = 16384.f * (float)acc1[i][j][h2 * 2 + 1] + 128.f * (float)acc2[i][j][h2 * 2 + 1];
                        float v0 = sa * sbv[j][0] * t0 + bv[j][0];
                        float v1 = sa * sbv[j][1] * t1 + bv[j][1];
                        if (LRELU_) { v0 = lrelu(v0); v1 = lrelu(v1); }
                        acc1[i][j][h2 * 2 + 0] = __float_as_int(v0);
                        acc1[i][j][h2 * 2 + 1] = __float_as_int(v1);
                        rmax = fmaxf(rmax, fmaxf(fabsf(v0), fabsf(v1)));
                    }
                    if (QOUT) {
                        rmax = fmaxf(rmax, __shfl_xor_sync(0xFFFFFFFFu, rmax, 1));
                        rmax = fmaxf(rmax, __shfl_xor_sync(0xFFFFFFFFu, rmax, 2));
                        if (q == 0) amax_atomic(&sf[lrow], rmax);
                    }
                }
            }
            if (QOUT) {
                __syncthreads();
                #pragma unroll
                for (int i = 0; i < MI; i++) {
                    #pragma unroll
                    for (int h2 = 0; h2 < 2; h2++) {
                        const int lrow = wm * MI * 16 + i * 16 + g + h2 * 8;
                        const int grow = rbase + lrow;
                        const float mx = sf[lrow];
                        const float inv = QMAX / fmaxf(mx, 1e-20f);
                        if (wn == 0 && q == 0) Os[grow] = mx;
                        #pragma unroll
                        for (int j = 0; j < 4; j++) {
                            const int col0 = wn * 32 + j * 8 + q * 2;
                            float v0 = __int_as_float(acc1[i][j][h2 * 2 + 0]);
                            float v1 = __int_as_float(acc1[i][j][h2 * 2 + 1]);
                            int p1, p2, r1, r2;
                            quant2(v0, inv, p1, p2);
                            quant2(v1, inv, r1, r2);
                            char2 o1; o1.x = (char)p1; o1.y = (char)r1;
                            char2 o2; o2.x = (char)p2; o2.y = (char)r2;
                            *reinterpret_cast<char2*>(Oq1 + (size_t)grow * OC + col0) = o1;
                            *reinterpret_cast<char2*>(Oq2 + (size_t)grow * OC + col0) = o2;
                        }
                    }
                }
                __syncthreads();
            } else {
                #pragma unroll
                for (int i = 0; i < MI; i++) {
                    #pragma unroll
                    for (int h2 = 0; h2 < 2; h2++) {
                        const int lrow = wm * MI * 16 + i * 16 + g + h2 * 8;
                        const int grow = rbase + lrow;
                        #pragma unroll
                        for (int j = 0; j < 4; j++) {
                            const int col0 = wn * 32 + j * 8 + q * 2;
                            float2 v;
                            v.x = __int_as_float(acc1[i][j][h2 * 2 + 0]);
                            v.y = __int_as_float(acc1[i][j][h2 * 2 + 1]);
                            *reinterpret_cast<float2*>(Of + (size_t)grow * OC + col0) = v;
                        }
                    }
                }
            }
            #pragma unroll
            for (int i = 0; i < MI; i++)
                #pragma unroll
                for (int j = 0; j < 4; j++)
                    #pragma unroll
                    for (int r = 0; r < 4; r++) { acc1[i][j][r] = 0; acc2[i][j][r] = 0; }
        }
    }
}

// ---------------------------------------------------------------------------
// Fused wc head + compositing
// ---------------------------------------------------------------------------
__global__ void __launch_bounds__(256)
lwcomp(const int8_t* __restrict__ Aq1, const int8_t* __restrict__ Aq2,
       const float* __restrict__ As,
       const int8_t* __restrict__ Bq1, const int8_t* __restrict__ Bq2,
       const float* __restrict__ Bs, const float* __restrict__ bias,
       const float* __restrict__ sigma, const float* __restrict__ dists,
       __nv_bfloat16* __restrict__ feath, __nv_bfloat16* __restrict__ featl,
       float* __restrict__ amax_out) {
    extern __shared__ char smem[];
    constexpr int MT = 128, NT = 64, K = HID;
    constexpr int NCH   = K / 64;
    constexpr int ASLAB = MT * 80;
    constexpr int BSLAB = NT * 80;
    constexpr int BOFF  = 2 * ASLAB;
    constexpr int BUF   = 2 * ASLAB + 2 * BSLAB;
    constexpr int WN = 2, WM = 4, MI = 2;
    constexpr int TSTR = 68;

    const uint32_t sb = smem_u32(smem);
    const int tid = threadIdx.x;
    const int lane = tid & 31, wid = tid >> 5;
    const int wn = wid % WN, wm = wid / WN;
    const int g = lane >> 2, q = lane & 3;
    const int rbase = blockIdx.x * MT;
    const int pb = blockIdx.x * 8;

    auto load_chunk = [&](int bufi, int c) {
        const uint32_t base = sb + bufi * BUF;
        const int k0 = c * 64;
        for (int idx = tid; idx < MT * 4; idx += 256) {
            const int row = idx >> 2, cc = idx & 3;
            const size_t go = (size_t)(rbase + row) * K + k0 + cc * 16;
            const uint32_t d = base + row * 80 + cc * 16;
            cpa16z(d,         Aq1 + go, 16);
            cpa16z(d + ASLAB, Aq2 + go, 16);
        }
        for (int idx = tid; idx < NT * 4; idx += 256) {
            const int row = idx >> 2, cc = idx & 3;
            const size_t go = (size_t)row * K + k0 + cc * 16;
            const uint32_t d = base + BOFF + row * 80 + cc * 16;
            cpa16z(d,         Bq1 + go, 16);
            cpa16z(d + BSLAB, Bq2 + go, 16);
        }
        asm volatile("cp.async.commit_group;" ::: "memory");
    };

    int acc1[MI][4][4], acc2[MI][4][4];
    #pragma unroll
    for (int i = 0; i < MI; i++)
        #pragma unroll
        for (int j = 0; j < 4; j++)
            #pragma unroll
            for (int r = 0; r < 4; r++) { acc1[i][j][r] = 0; acc2[i][j][r] = 0; }

    load_chunk(0, 0);
    int buf = 0, nbuf = 1;
    for (int c = 0; c < NCH; c++) {
        if (c + 1 < NCH) {
            load_chunk(nbuf, c + 1);
            asm volatile("cp.async.wait_group 1;" ::: "memory");
        } else {
            asm volatile("cp.async.wait_group 0;" ::: "memory");
        }
        __syncthreads();
        const uint32_t Ab = sb + buf * BUF;
        const uint32_t Bb = Ab + BOFF;
        #pragma unroll
        for (int kk = 0; kk < 2; kk++) {
            const int koff = kk * 32;
            uint32_t a1[MI][4], a2[MI][4];
            #pragma unroll
            for (int i = 0; i < MI; i++) {
                const uint32_t r0 = ldm_a_addr(Ab + (uint32_t)(wm * MI * 16 + i * 16) * 80 + koff, lane);
                ldm_x4(a1[i], r0);
                ldm_x4(a2[i], r0 + ASLAB);
            }
            uint32_t b1[4][2], b2[4][2];
            #pragma unroll
            for (int jp = 0; jp < 2; jp++) {
                const uint32_t r0 = ldm_b_addr(Bb + (uint32_t)(wn * 32 + jp * 16) * 80 + koff, lane);
                uint32_t t[4];
                ldm_x4(t, r0);
                b1[2 * jp][0] = t[0]; b1[2 * jp][1] = t[1];
                b1[2 * jp + 1][0] = t[2]; b1[2 * jp + 1][1] = t[3];
                ldm_x4(t, r0 + BSLAB);
                b2[2 * jp][0] = t[0]; b2[2 * jp][1] = t[1];
                b2[2 * jp + 1][0] = t[2]; b2[2 * jp + 1][1] = t[3];
            }
            #pragma unroll
            for (int i = 0; i < MI; i++)
                #pragma unroll
                for (int j = 0; j < 4; j++) {
                    imma16832(acc1[i][j], a1[i], b1[j]);
                    imma16832(acc2[i][j], a1[i], b2[j]);
                    imma16832(acc2[i][j], a2[i], b1[j]);
                }
        }
        buf = nbuf; nbuf = (nbuf == 2) ? 0 : nbuf + 1;
    }
    __syncthreads();

    float* tile = reinterpret_cast<float*>(smem);
    float* wg   = reinterpret_cast<float*>(smem) + MT * TSTR;
    float* sch  = wg + 8 * MM;
    #pragma unroll
    for (int j = 0; j < 4; j++) {
        const int col0 = wn * 32 + j * 8 + q * 2;
        const float sb0 = Bs[col0], sb1 = Bs[col0 + 1];
        const float b0 = bias[col0], b1 = bias[col0 + 1];
        #pragma unroll
        for (int i = 0; i < MI; i++) {
            #pragma unroll
            for (int h = 0; h < 2; h++) {
                const int lrow = wm * MI * 16 + i * 16 + g + h * 8;
                const float sa = As[rbase + lrow] * (1.f / QDEN);
                float t0 = 16384.f * (float)acc1[i][j][h * 2 + 0] + 128.f * (float)acc2[i][j][h * 2 + 0];
                float t1 = 16384.f * (float)acc1[i][j][h * 2 + 1] + 128.f * (float)acc2[i][j][h * 2 + 1];
                float2 v;
                v.x = sa * sb0 * t0 + b0;
                v.y = sa * sb1 * t1 + b1;
                *reinterpret_cast<float2*>(&tile[lrow * TSTR + col0]) = v;
            }
        }
    }
    if (tid < 8) {
        const int pix = pb + tid;
        float T = 1.f;
        #pragma unroll
        for (int m2 = 0; m2 < MM; m2++) {
            float sg = sigma[pix * MM + m2];
            sg = sg > 0.f ? sg : 0.f;
            float a = 1.f - expf(-sg * dists[pix * MM + m2]);
            wg[tid * MM + m2] = a * T;
            T *= (1.f - a + 1e-10f);
        }
    }
    if (tid >= 64 && tid < 128) sch[tid - 64] = 0.f;
    __syncthreads();

    const int c0 = tid & 63;
    float lm = 0.f;
    #pragma unroll
    for (int t2 = 0; t2 < 2; t2++) {
        const int o = tid + t2 * 256;
        const int pix = o >> 6;
        float acc = 0.f;
        #pragma unroll
        for (int m2 = 0; m2 < MM; m2++)
            acc += wg[pix * MM + m2] * tile[(pix * MM + m2) * TSTR + c0];
        __nv_bfloat16 hbf = __float2bfloat16(acc);
        feath[(size_t)(pb + pix) * COL + c0] = hbf;
        featl[(size_t)(pb + pix) * COL + c0] = __float2bfloat16(acc - __bfloat162float(hbf));
        lm = fmaxf(lm, fabsf(acc));
    }
    amax_atomic(&sch[c0], lm);
    __syncthreads();
    if (tid < 64) amax_atomic(&amax_out[tid], sch[tid]);
}

// ---------------------------------------------------------------------------
// CNN int8 conv: 256 threads, tile 64 px x 128 ch, triple-buffered.
// ---------------------------------------------------------------------------
template<int TAPS, int K, bool HAS_BIAS, bool HAS_RES, bool HAS_MOD, bool DO_AMAX>
__global__ void __launch_bounds__(256)
conv_q(const int8_t* __restrict__ Aq1, const int8_t* __restrict__ Aq2,
       const int8_t* __restrict__ Wq1, const int8_t* __restrict__ Wq2,
       const float* __restrict__ Ts, const float* __restrict__ bias,
       const __nv_bfloat16* __restrict__ ResH, const __nv_bfloat16* __restrict__ ResL,
       const float* __restrict__ zc, int modoff,
       __nv_bfloat16* __restrict__ Chi, __nv_bfloat16* __restrict__ Clo,
       float* __restrict__ amax_out) {
    extern __shared__ char smem[];
    constexpr int KCH    = K / 64;
    constexpr int NCHUNK = TAPS * KCH;
    constexpr int ASLAB  = 64 * 80;
    constexpr int BSLAB  = 128 * 80;
    constexpr int BOFF   = 2 * ASLAB;
    constexpr int BUF    = 2 * ASLAB + 2 * BSLAB;
    constexpr int MI     = 2;

    const uint32_t sb = smem_u32(smem);
    const int tid = threadIdx.x;
    const int lane = tid & 31, wid = tid >> 5;
    const int wn = wid & 3, wm = wid >> 2;
    const int g = lane >> 2, q = lane & 3;
    const int o0 = blockIdx.y * 128;
    const int py0 = (int)blockIdx.x >> 1;
    const int px0 = ((int)blockIdx.x & 1) << 6;

    auto load_chunk = [&](int bufi, int chunk) {
        const int tap = (TAPS == 9) ? (chunk / KCH) : 0;
        const int k0  = ((TAPS == 9) ? (chunk - tap * KCH) : chunk) * 64;
        const uint32_t base = sb + bufi * BUF;
        {
            const int row = tid >> 2, cc = tid & 3;
            uint32_t sz = 16;
            int pix;
            if (TAPS == 9) {
                const int dy = tap / 3 - 1, dx = tap % 3 - 1;
                const int py = py0 + dy, px = px0 + row + dx;
                const bool ok = (py >= 0) && (py < HH) && (px >= 0) && (px < WW);
                sz = ok ? 16u : 0u;
                pix = ok ? (py * WW + px) : 0;
            } else {
                pix = py0 * WW + px0 + row;
            }
            const size_t go = (size_t)pix * K + k0 + cc * 16;
            const uint32_t d = base + row * 80 + cc * 16;
            cpa16z(d,         Aq1 + go, sz);
            cpa16z(d + ASLAB, Aq2 + go, sz);
        }
        for (int idx = tid; idx < 128 * 4; idx += 256) {
            const int row = idx >> 2, cc = idx & 3;
            const size_t go = (size_t)tap * (HID * K) + (size_t)(o0 + row) * K + k0 + cc * 16;
            const uint32_t d = base + BOFF + row * 80 + cc * 16;
            cpa16z(d,         Wq1 + go, 16);
            cpa16z(d + BSLAB, Wq2 + go, 16);
        }
        asm volatile("cp.async.commit_group;" ::: "memory");
    };

    int acc1[MI][4][4], acc2[MI][4][4];
    #pragma unroll
    for (int i = 0; i < MI; i++)
        #pragma unroll
        for (int j = 0; j < 4; j++)
            #pragma unroll
            for (int r = 0; r < 4; r++) { acc1[i][j][r] = 0; acc2[i][j][r] = 0; }

    load_chunk(0, 0);
    int buf = 0, nbuf = 1;
    for (int c = 0; c < NCHUNK; c++) {
        if (c + 1 < NCHUNK) {
            load_chunk(nbuf, c + 1);
            asm volatile("cp.async.wait_group 1;" ::: "memory");
        } else {
            asm volatile("cp.async.wait_group 0;" ::: "memory");
        }
        __syncthreads();
        const uint32_t Ab = sb + buf * BUF;
        const uint32_t Bb = Ab + BOFF;
        #pragma unroll
        for (int kk = 0; kk < 2; kk++) {
            const int koff = kk * 32;
            uint32_t a1[MI][4], a2[MI][4];
            #pragma unroll
            for (int i = 0; i < MI; i++) {
                const uint32_t r0 = ldm_a_addr(Ab + (uint32_t)(wm * 32 + i * 16) * 80 + koff, lane);
                ldm_x4(a1[i], r0);
                ldm_x4(a2[i], r0 + ASLAB);
            }
            uint32_t b1[4][2], b2[4][2];
            #pragma unroll
            for (int jp = 0; jp < 2; jp++) {
                const uint32_t r0 = ldm_b_addr(Bb + (uint32_t)(wn * 32 + jp * 16) * 80 + koff, lane);
                uint32_t t[4];
                ldm_x4(t, r0);
                b1[2 * jp][0] = t[0]; b1[2 * jp][1] = t[1];
                b1[2 * jp + 1][0] = t[2]; b1[2 * jp + 1][1] = t[3];
                ldm_x4(t, r0 + BSLAB);
                b2[2 * jp][0] = t[0]; b2[2 * jp][1] = t[1];
                b2[2 * jp + 1][0] = t[2]; b2[2 * jp + 1][1] = t[3];
            }
            #pragma unroll
            for (int i = 0; i < MI; i++)
                #pragma unroll
                for (int j = 0; j < 4; j++) {
                    imma16832(acc1[i][j], a1[i], b1[j]);
                    imma16832(acc2[i][j], a1[i], b2[j]);
                    imma16832(acc2[i][j], a2[i], b1[j]);
                }
        }
        buf = nbuf; nbuf = (nbuf == 2) ? 0 : nbuf + 1;
    }

    __syncthreads();
    float* sch = reinterpret_cast<float*>(smem);
    if (DO_AMAX) {
        if (tid < 128) sch[tid] = 0.f;
        __syncthreads();
    }
    #pragma unroll
    for (int j = 0; j < 4; j++) {
        const int cl = wn * 32 + j * 8 + q * 2;
        const int colg = o0 + cl;
        const float t0 = Ts[colg], t1 = Ts[colg + 1];
        const float b0 = HAS_BIAS ? bias[colg]     : 0.f;
        const float b1 = HAS_BIAS ? bias[colg + 1] : 0.f;
        float sc0 = 1.f, sc1 = 1.f, sh0 = 0.f, sh1 = 0.f;
        if (HAS_MOD) {
            sc0 = zc[modoff + colg] + 1.f;       sc1 = zc[modoff + colg + 1] + 1.f;
            sh0 = zc[modoff + HID + colg];       sh1 = zc[modoff + HID + colg + 1];
        }
        float lm0 = 0.f, lm1 = 0.f;
        #pragma unroll
        for (int i = 0; i < MI; i++) {
            #pragma unroll
            for (int h = 0; h < 2; h++) {
                const int pix = py0 * WW + px0 + wm * 32 + i * 16 + g + h * 8;
                float v0 = t0 * (16384.f * (float)acc1[i][j][h * 2 + 0] + 128.f * (float)acc2[i][j][h * 2 + 0]) + b0;
                float v1 = t1 * (16384.f * (float)acc1[i][j][h * 2 + 1] + 128.f * (float)acc2[i][j][h * 2 + 1]) + b1;
                if (HAS_RES) {
                    __nv_bfloat162 rh = *reinterpret_cast<const __nv_bfloat162*>(ResH + (size_t)pix * HID + colg);
                    __nv_bfloat162 rl = *reinterpret_cast<const __nv_bfloat162*>(ResL + (size_t)pix * HID + colg);
                    v0 += __bfloat162float(rh.x) + __bfloat162float(rl.x);
                    v1 += __bfloat162float(rh.y) + __bfloat162float(rl.y);
                }
                if (HAS_MOD) { v0 = v0 * sc0 + sh0; v1 = v1 * sc1 + sh1; }
                v0 = lrelu(v0); v1 = lrelu(v1);
                if (DO_AMAX) { lm0 = fmaxf(lm0, fabsf(v0)); lm1 = fmaxf(lm1, fabsf(v1)); }
                __nv_bfloat162 hp = __floats2bfloat162_rn(v0, v1);
                float r0 = v0 - __bfloat162float(hp.x);
                float r1 = v1 - __bfloat162float(hp.y);
                __nv_bfloat162 lp = __floats2bfloat162_rn(r0, r1);
                *reinterpret_cast<__nv_bfloat162*>(Chi + (size_t)pix * HID + colg) = hp;
                *reinterpret_cast<__nv_bfloat162*>(Clo + (size_t)pix * HID + colg) = lp;
            }
        }
        if (DO_AMAX) {
            #pragma unroll
            for (int off = 4; off <= 16; off <<= 1) {
                lm0 = fmaxf(lm0, __shfl_xor_sync(0xFFFFFFFFu, lm0, off));
                lm1 = fmaxf(lm1, __shfl_xor_sync(0xFFFFFFFFu, lm1, off));
            }
            if (g == 0) {
                amax_atomic(&sch[cl], lm0);
                amax_atomic(&sch[cl + 1], lm1);
            }
        }
    }
    if (DO_AMAX) {
        __syncthreads();
        if (tid < 128) amax_atomic(&amax_out[o0 + tid], sch[tid]);
    }
}

// ---------------------------------------------------------------------------
// sigma (warp per sample)
// ---------------------------------------------------------------------------
__global__ void sigma_q(const int8_t* __restrict__ A1, const int8_t* __restrict__ A2,
                        const float* __restrict__ As, const float* __restrict__ wsig,
                        const float* __restrict__ bsig, float* __restrict__ out) {
    int s = (blockIdx.x * blockDim.x + threadIdx.x) >> 5;
    int lane = threadIdx.x & 31;
    if (s >= S_TOT) return;
    const char4* p1 = reinterpret_cast<const char4*>(A1 + (size_t)s * HID);
    const char4* p2 = reinterpret_cast<const char4*>(A2 + (size_t)s * HID);
    float acc = 0.f;
    #pragma unroll
    for (int t = 0; t < 2; t++) {
        int idx = lane + 32 * t;
        char4 c1 = p1[idx];
        char4 c2 = p2[idx];
        int k = idx * 4;
        acc += (float)(c1.x * 128 + c2.x) * wsig[k + 0];
        acc += (float)(c1.y * 128 + c2.y) * wsig[k + 1];
        acc += (float)(c1.z * 128 + c2.z) * wsig[k + 2];
        acc += (float)(c1.w * 128 + c2.w) * wsig[k + 3];
    }
    #pragma unroll
    for (int off = 16; off; off >>= 1) acc += __shfl_xor_sync(0xFFFFFFFFu, acc, off);
    if (lane == 0) out[s] = acc * (As[s] * (1.f / QMAX)) + bsig[0];
}

// ---------------------------------------------------------------------------
// Final 1x1 conv to 3 channels (warp per pixel)
// ---------------------------------------------------------------------------
__global__ void final_conv(const __nv_bfloat16* __restrict__ InH,
                           const __nv_bfloat16* __restrict__ InL,
                           const float* __restrict__ w,
                           const float* __restrict__ b, float* __restrict__ out) {
    int warp = (blockIdx.x * blockDim.x + threadIdx.x) >> 5;
    int lane = threadIdx.x & 31;
    if (warp >= HWPIX) return;
    const __nv_bfloat16* ph = InH + (size_t)warp * HID;
    const __nv_bfloat16* pl = InL + (size_t)warp * HID;
    float a0 = 0.f, a1 = 0.f, a2 = 0.f;
    #pragma unroll
    for (int t = 0; t < 8; t++) {
        int i = lane + 32 * t;
        float v = __bfloat162float(ph[i]) + __bfloat162float(pl[i]);
        a0 += v * w[i];
        a1 += v * w[HID + i];
        a2 += v * w[2 * HID + i];
    }
    #pragma unroll
    for (int off = 16; off; off >>= 1) {
        a0 += __shfl_xor_sync(0xFFFFFFFFu, a0, off);
        a1 += __shfl_xor_sync(0xFFFFFFFFu, a1, off);
        a2 += __shfl_xor_sync(0xFFFFFFFFu, a2, off);
    }
    if (lane == 0) {
        out[warp]             = a0 + b[0];
        out[HWPIX + warp]     = a1 + b[1];
        out[2 * HWPIX + warp] = a2 + b[2];
    }
}

// ---------------------------------------------------------------------------
// Launch
// ---------------------------------------------------------------------------
extern "C" void kernel_launch(void* const* d_in, const int* in_sizes, int n_in,
                              void* d_out, int out_size) {
    const float* x     = (const float*)d_in[0];
    const float* m     = (const float*)d_in[1];
    const float* z     = (const float*)d_in[2];
    const float* dists = (const float*)d_in[3];
    const float* w1    = (const float*)d_in[4];
    const float* b1    = (const float*)d_in[5];
    const float* wma   = (const float*)d_in[6];
    const float* ml_w  = (const float*)d_in[7];
    const float* ml_wa = (const float*)d_in[8];
    const float* ml_ba = (const float*)d_in[9];
    const float* ml_wb = (const float*)d_in[10];
    const float* ml_bb = (const float*)d_in[11];
    const float* wsig  = (const float*)d_in[12];
    const float* bsig  = (const float*)d_in[13];
    const float* wc    = (const float*)d_in[14];
    const float* bc    = (const float*)d_in[15];
    const float* wz    = (const float*)d_in[16];
    const float* bz    = (const float*)d_in[17];
    const float* c1_w  = (const float*)d_in[18];
    const float* c1_b  = (const float*)d_in[19];
    const float* c2a_w = (const float*)d_in[20];
    const float* c2a_b = (const float*)d_in[21];
    const float* c2b_w = (const float*)d_in[22];
    const float* c3a_w = (const float*)d_in[23];
    const float* c3a_b = (const float*)d_in[24];
    const float* c3b_w = (const float*)d_in[25];
    const float* c4a_w = (const float*)d_in[26];
    const float* c4a_b = (const float*)d_in[27];
    const float* c4b_w = (const float*)d_in[28];
    const float* c4b_b = (const float*)d_in[29];
    const float* c4_w  = (const float*)d_in[30];
    const float* c4_b  = (const float*)d_in[31];
    float* out = (float*)d_out;

    int8_t *xq1, *xq2, *aq1, *aq2, *bq1, *bq2;
    int8_t *w1q1, *w1q2, *wmq1, *wmq2, *wcq1, *wcq2, *cq1, *cq2, *cwq1, *cwq2;
    float *xs, *as, *bsc, *w1s, *wms, *wcs, *wt3f, *cts, *camax;
    __nv_bfloat16 *yah, *yal, *ybh, *ybl, *ych, *ycl, *fth, *ftl;
    float *sig, *zcv, *be;
    cudaGetSymbolAddress((void**)&xq1, d_xq1);
    cudaGetSymbolAddress((void**)&xq2, d_xq2);
    cudaGetSymbolAddress((void**)&xs,  d_xs);
    cudaGetSymbolAddress((void**)&aq1, d_aq1);
    cudaGetSymbolAddress((void**)&aq2, d_aq2);
    cudaGetSymbolAddress((void**)&as,  d_as);
    cudaGetSymbolAddress((void**)&bq1, d_bq1);
    cudaGetSymbolAddress((void**)&bq2, d_bq2);
    cudaGetSymbolAddress((void**)&bsc, d_bsc);
    cudaGetSymbolAddress((void**)&w1q1, d_w1q1);
    cudaGetSymbolAddress((void**)&w1q2, d_w1q2);
    cudaGetSymbolAddress((void**)&w1s,  d_w1s);
    cudaGetSymbolAddress((void**)&wmq1, d_wmq1);
    cudaGetSymbolAddress((void**)&wmq2, d_wmq2);
    cudaGetSymbolAddress((void**)&wms,  d_wms);
    cudaGetSymbolAddress((void**)&wcq1, d_wcq1);
    cudaGetSymbolAddress((void**)&wcq2, d_wcq2);
    cudaGetSymbolAddress((void**)&wcs,  d_wcs);
    cudaGetSymbolAddress((void**)&wt3f, d_wt3f);
    cudaGetSymbolAddress((void**)&cwq1, d_cwq1);
    cudaGetSymbolAddress((void**)&cwq2, d_cwq2);
    cudaGetSymbolAddress((void**)&cts,  d_cts);
    cudaGetSymbolAddress((void**)&camax, d_camax);
    cudaGetSymbolAddress((void**)&cq1, d_cq1);
    cudaGetSymbolAddress((void**)&cq2, d_cq2);
    cudaGetSymbolAddress((void**)&yah, d_yah);
    cudaGetSymbolAddress((void**)&yal, d_yal);
    cudaGetSymbolAddress((void**)&ybh, d_ybh);
    cudaGetSymbolAddress((void**)&ybl, d_ybl);
    cudaGetSymbolAddress((void**)&ych, d_ych);
    cudaGetSymbolAddress((void**)&ycl, d_ycl);
    cudaGetSymbolAddress((void**)&fth, d_feath);
    cudaGetSymbolAddress((void**)&ftl, d_featl);
    cudaGetSymbolAddress((void**)&sig, d_sig);
    cudaGetSymbolAddress((void**)&zcv, d_zc);
    cudaGetSymbolAddress((void**)&be,  d_beta);

    const int TWF = 9 * HID * HID;
    const int SM_L1 = 2 * 3 * (256 * 80) + 3 * (2 * 2 * 64 * 80) + 256;   // 184576
    const int SM_LH = 2 * 4 * (256 * 80) + 3 * (2 * 2 * 64 * 80) + 256;   // 225536
    const int SM_LC = 3 * (2 * 128 * 80 + 2 * 64 * 80);                    // 92160
    const int SMCV  = 3 * (2 * 64 * 80 + 2 * 128 * 80);                    // 92160

    auto L1 = imma_brg<512, 64, 8, 256, KQ1, true, true>;
    auto LH = imma_brg<512, 64, 8, 256, HID, true, true>;
    auto CV1  = conv_q<1, COL, true,  false, false, true >;
    auto CVA  = conv_q<9, HID, true,  false, false, true >;
    auto CVB  = conv_q<9, HID, false, true,  true,  true >;
    auto CV4A = conv_q<1, HID, true,  false, false, true >;
    auto CV4B = conv_q<1, HID, true,  true,  false, false>;

    cudaFuncSetAttribute(L1,     cudaFuncAttributeMaxDynamicSharedMemorySize, SM_L1);
    cudaFuncSetAttribute(LH,     cudaFuncAttributeMaxDynamicSharedMemorySize, SM_LH);
    cudaFuncSetAttribute(lwcomp, cudaFuncAttributeMaxDynamicSharedMemorySize, SM_LC);
    cudaFuncSetAttribute(CV1,  cudaFuncAttributeMaxDynamicSharedMemorySize, SMCV);
    cudaFuncSetAttribute(CVA,  cudaFuncAttributeMaxDynamicSharedMemorySize, SMCV);
    cudaFuncSetAttribute(CVB,  cudaFuncAttributeMaxDynamicSharedMemorySize, SMCV);
    cudaFuncSetAttribute(CV4A, cudaFuncAttributeMaxDynamicSharedMemorySize, SMCV);
    cudaFuncSetAttribute(CV4B, cudaFuncAttributeMaxDynamicSharedMemorySize, SMCV);

    const int GRB = S_TOT / 512;   // 512 (64 rows x 8 m-tiles per CTA)

    prep_vec<<<448, 256>>>(z, ml_wa, ml_ba, ml_wb, ml_bb, wz, bz);        // 1
    prep_xq<<<S_TOT / 8, 256>>>(x, m);                                    // 2
    prep_w1q<<<HID / 8, 256>>>(w1, wma);                                  // 3
    L1<<<GRB, 512, SM_L1>>>(xq1, xq2, xs, w1q1, w1q2, w1s, b1,
                            aq1, aq2, as, nullptr, HID);                  // 4 <-- ncu
    prep_wmq<<<5 * HID / 8, 256>>>(ml_w);
    prep_wcq<<<COL / 8, 256>>>(wc);
    reset_amax<<<7, 256>>>();

    // --- MLP ---
    LH<<<GRB, 512, SM_LH>>>(aq1, aq2, as, wmq1 + 0 * 65536, wmq2 + 0 * 65536, wms + 0,
                            be + 0,    bq1, bq2, bsc, nullptr, HID);
    LH<<<GRB, 512, SM_LH>>>(bq1, bq2, bsc, wmq1 + 1 * 65536, wmq2 + 1 * 65536, wms + 256,
                            be + 256,  aq1, aq2, as, nullptr, HID);
    LH<<<GRB, 512, SM_LH>>>(aq1, aq2, as, wmq1 + 2 * 65536, wmq2 + 2 * 65536, wms + 512,
                            be + 512,  bq1, bq2, bsc, nullptr, HID);
    sigma_q<<<S_TOT / 8, 256>>>(bq1, bq2, bsc, wsig, bsig, sig);
    LH<<<GRB, 512, SM_LH>>>(bq1, bq2, bsc, wmq1 + 3 * 65536, wmq2 + 3 * 65536, wms + 768,
                            be + 768,  aq1, aq2, as, nullptr, HID);
    LH<<<GRB, 512, SM_LH>>>(aq1, aq2, as, wmq1 + 4 * 65536, wmq2 + 4 * 65536, wms + 1024,
                            be + 1024, bq1, bq2, bsc, nullptr, HID);

    // --- fused wc head + compositing (feat + camax[0]) ---
    lwcomp<<<S_TOT / 128, 256, SM_LC>>>(bq1, bq2, bsc, wcq1, wcq2, wcs, bc,
                                        sig, dists, fth, ftl, camax + 0 * HID);

    // --- CNN weight transposes ---
    prep_twf<<<(TWF + 255) / 256, 256>>>(c2a_w, wt3f + 0 * TWF);
    prep_twf<<<(TWF + 255) / 256, 256>>>(c2b_w, wt3f + 1 * TWF);
    prep_twf<<<(TWF + 255) / 256, 256>>>(c3a_w, wt3f + 2 * TWF);
    prep_twf<<<(TWF + 255) / 256, 256>>>(c3b_w, wt3f + 3 * TWF);

    // --- CNN (int8 IMMA, runtime scale folding; fused quant+wreq) ---
    dim3 gC(2 * HH, 2);
    const int NQ  = (HWPIX * HID + 255) / 256;
    const int NQF = (HWPIX * COL + 255) / 256;

    qa_wr<COL, 1, COL><<<NQF + 32, 256>>>(fth, ftl, camax + 0 * HID, cq1, cq2,
                                          c1_w, cwq1, cwq2, cts, NQF);
    CV1<<<gC, 256, SMCV>>>(cq1, cq2, cwq1, cwq2, cts, c1_b, nullptr, nullptr,
                           nullptr, 0, yah, yal, camax + 1 * HID);

    qa_wr<HID, 9, HID><<<NQ + 32, 256>>>(yah, yal, camax + 1 * HID, cq1, cq2,
                                         wt3f + 0 * TWF, cwq1, cwq2, cts, NQ);
    CVA<<<gC, 256, SMCV>>>(cq1, cq2, cwq1, cwq2, cts, c2a_b, nullptr, nullptr,
                           nullptr, 0, ybh, ybl, camax + 2 * HID);

    qa_wr<HID, 9, HID><<<NQ + 32, 256>>>(ybh, ybl, camax + 2 * HID, cq1, cq2,
                                         wt3f + 1 * TWF, cwq1, cwq2, cts, NQ);
    CVB<<<gC, 256, SMCV>>>(cq1, cq2, cwq1, cwq2, cts, nullptr, yah, yal,
                           zcv, 0, ych, ycl, camax + 3 * HID);

    qa_wr<HID, 9, HID><<<NQ + 32, 256>>>(ych, ycl, camax + 3 * HID, cq1, cq2,
                                         wt3f + 2 * TWF, cwq1, cwq2, cts, NQ);
    CVA<<<gC, 256, SMCV>>>(cq1, cq2, cwq1, cwq2, cts, c3a_b, nullptr, nullptr,
                           nullptr, 0, ybh, ybl, camax + 4 * HID);

    qa_wr<HID, 9, HID><<<NQ + 32, 256>>>(ybh, ybl, camax + 4 * HID, cq1, cq2,
                                         wt3f + 3 * TWF, cwq1, cwq2, cts, NQ);
    CVB<<<gC, 256, SMCV>>>(cq1, cq2, cwq1, cwq2, cts, nullptr, ych, ycl,
                           zcv, 512, yah, yal, camax + 5 * HID);

    qa_wr<HID, 1, HID><<<NQ + 32, 256>>>(yah, yal, camax + 5 * HID, cq1, cq2,
                                         c4a_w, cwq1, cwq2, cts, NQ);
    CV4A<<<gC, 256, SMCV>>>(cq1, cq2, cwq1, cwq2, cts, c4a_b, nullptr, nullptr,
                            nullptr, 0, ybh, ybl, camax + 6 * HID);

    qa_wr<HID, 1, HID><<<NQ + 32, 256>>>(ybh, ybl, camax + 6 * HID, cq1, cq2,
                                         c4b_w, cwq1, cwq2, cts, NQ);
    CV4B<<<gC, 256, SMCV>>>(cq1, cq2, cwq1, cwq2, cts, c4b_b, yah, yal,
                            nullptr, 0, ych, ycl, nullptr);

    final_conv<<<HWPIX / 8, 256>>>(ych, ycl, c4_w, c4_b, out);

    (void)in_sizes; (void)n_in; (void)out_size;
}

// round 16
// speedup vs baseline: 1.0617x; 1.0617x over previous
#include <cuda_runtime.h>
#include <cuda_bf16.h>
#include <cstdint>

// ---------------------------------------------------------------------------
// Problem constants
// ---------------------------------------------------------------------------
#define HH      128
#define WW      128
#define MM      16
#define CIN     128
#define NC      7
#define HID     256
#define STY     256
#define COL     64
#define HWPIX   (HH * WW)            // 16384
#define S_TOT   (HWPIX * MM)         // 262144
#define KQ1     192                  // padded K for layer 1

#define QMAX    16256.0f             // 127 * 128
#define QDEN    (16256.0f * 16256.0f)

// ---------------------------------------------------------------------------
// Scratch (device globals)
// ---------------------------------------------------------------------------
__device__ int8_t d_xq1[(size_t)S_TOT * KQ1];
__device__ int8_t d_xq2[(size_t)S_TOT * KQ1];
__device__ float  d_xs[S_TOT];
__device__ int8_t d_aq1[(size_t)S_TOT * HID];
__device__ int8_t d_aq2[(size_t)S_TOT * HID];
__device__ float  d_as[S_TOT];
__device__ int8_t d_bq1[(size_t)S_TOT * HID];
__device__ int8_t d_bq2[(size_t)S_TOT * HID];
__device__ float  d_bsc[S_TOT];
__device__ int8_t d_w1q1[HID * KQ1];
__device__ int8_t d_w1q2[HID * KQ1];
__device__ float  d_w1s[HID];
__device__ int8_t d_wmq1[5 * HID * HID];
__device__ int8_t d_wmq2[5 * HID * HID];
__device__ float  d_wms[5 * HID];
__device__ int8_t d_wcq1[COL * HID];
__device__ int8_t d_wcq2[COL * HID];
__device__ float  d_wcs[COL];
// CNN: fp transposed 3x3 weights, runtime-requantized int8 weights, scales
__device__ float  d_wt3f[4 * 9 * HID * HID];     // [conv][tap][O][K] fp32
__device__ int8_t d_cwq1[9 * HID * HID];
__device__ int8_t d_cwq2[9 * HID * HID];
__device__ float  d_cts[HID];
__device__ float  d_camax[7 * HID];
// CNN activations: bf16 hi/lo pairs + int8 quantized planes
__device__ __nv_bfloat16 d_yah[HWPIX * HID];
__device__ __nv_bfloat16 d_yal[HWPIX * HID];
__device__ __nv_bfloat16 d_ybh[HWPIX * HID];
__device__ __nv_bfloat16 d_ybl[HWPIX * HID];
__device__ __nv_bfloat16 d_ych[HWPIX * HID];
__device__ __nv_bfloat16 d_ycl[HWPIX * HID];
__device__ __nv_bfloat16 d_feath[HWPIX * COL];
__device__ __nv_bfloat16 d_featl[HWPIX * COL];
__device__ int8_t d_cq1[HWPIX * HID];
__device__ int8_t d_cq2[HWPIX * HID];
__device__ float d_sig[S_TOT];
__device__ float d_alpha[5 * HID];
__device__ float d_beta[5 * HID];
__device__ float d_zc[4 * HID];

static __device__ __forceinline__ float lrelu(float v) {
    return v > 0.f ? v : 0.2f * v;
}

static __device__ __forceinline__ uint32_t smem_u32(const void* p) {
    uint32_t a;
    asm("{ .reg .u64 t; cvta.to.shared.u64 t, %1; cvt.u32.u64 %0, t; }" : "=r"(a) : "l"(p));
    return a;
}

static __device__ __forceinline__ void cpa16z(uint32_t dst, const void* src, uint32_t sz) {
    asm volatile("cp.async.cg.shared.global [%0], [%1], 16, %2;"
                 :: "r"(dst), "l"(src), "r"(sz));
}

static __device__ __forceinline__ void ldm_x4(uint32_t* r, uint32_t addr) {
    asm volatile("ldmatrix.sync.aligned.m8n8.x4.shared.b16 {%0,%1,%2,%3}, [%4];"
                 : "=r"(r[0]), "=r"(r[1]), "=r"(r[2]), "=r"(r[3]) : "r"(addr));
}

static __device__ __forceinline__ void imma16832(int* d, const uint32_t* a, const uint32_t* b) {
    asm volatile(
        "mma.sync.aligned.m16n8k32.row.col.s32.s8.s8.s32 "
        "{%0,%1,%2,%3}, {%4,%5,%6,%7}, {%8,%9}, {%0,%1,%2,%3};"
        : "+r"(d[0]), "+r"(d[1]), "+r"(d[2]), "+r"(d[3])
        : "r"(a[0]), "r"(a[1]), "r"(a[2]), "r"(a[3]), "r"(b[0]), "r"(b[1]));
}

static __device__ __forceinline__ uint32_t ldm_a_addr(uint32_t base, int lane) {
    return base + (uint32_t)(lane & 15) * 80 + (uint32_t)((lane >> 4) << 4);
}
static __device__ __forceinline__ uint32_t ldm_b_addr(uint32_t base, int lane) {
    const int n = (lane & 7) + ((lane >= 16) ? 8 : 0);
    const int k16 = ((lane >> 3) & 1) << 4;
    return base + (uint32_t)n * 80 + (uint32_t)k16;
}

static __device__ __forceinline__ void quant2(float v, float inv, int& q1, int& q2) {
    float qf = rintf(v * inv);
    int   q  = (int)qf;
    q1 = (int)rintf(qf * (1.f / 128.f));
    q2 = q - (q1 << 7);
}

static __device__ __forceinline__ void amax_atomic(float* addr, float v) {
    atomicMax(reinterpret_cast<int*>(addr), __float_as_int(v));
}

// ---------------------------------------------------------------------------
// Prep kernels
// ---------------------------------------------------------------------------
__global__ void prep_vec(const float* __restrict__ z,
                         const float* __restrict__ wa, const float* __restrict__ ba,
                         const float* __restrict__ wb, const float* __restrict__ bb,
                         const float* __restrict__ wz, const float* __restrict__ bz) {
    int warp = (blockIdx.x * blockDim.x + threadIdx.x) >> 5;
    int lane = threadIdx.x & 31;
    if (warp >= 3584) return;
    const float* row; float bias; float* out;
    if (warp < 1280)      { row = wa + (size_t)warp * STY; bias = ba[warp]; out = d_alpha + warp; }
    else if (warp < 2560) { int i = warp - 1280; row = wb + (size_t)i * STY; bias = bb[i]; out = d_beta + i; }
    else                  { int i = warp - 2560; row = wz + (size_t)i * STY; bias = bz[i]; out = d_zc + i; }
    float acc = 0.f;
    #pragma unroll
    for (int t = 0; t < 8; t++) acc += z[lane + 32 * t] * row[lane + 32 * t];
    #pragma unroll
    for (int off = 16; off; off >>= 1) acc += __shfl_xor_sync(0xFFFFFFFFu, acc, off);
    if (lane == 0) *out = acc + bias;
}

static __device__ __forceinline__ float warp_amax(float a) {
    #pragma unroll
    for (int off = 16; off; off >>= 1) a = fmaxf(a, __shfl_xor_sync(0xFFFFFFFFu, a, off));
    return a;
}

__global__ void prep_xq(const float* __restrict__ x, const float* __restrict__ m) {
    int s = blockIdx.x * 8 + (threadIdx.x >> 5);
    int lane = threadIdx.x & 31;
    if (s >= S_TOT) return;
    float v[6];
    #pragma unroll
    for (int t = 0; t < 6; t++) {
        int c = lane + 32 * t;
        float val = 0.f;
        if (c < CIN)           val = x[(size_t)s * CIN + c];
        else if (c < CIN + NC) val = m[(size_t)s * NC + (c - CIN)];
        v[t] = val;
    }
    float am = 0.f;
    #pragma unroll
    for (int t = 0; t < 6; t++) am = fmaxf(am, fabsf(v[t]));
    am = warp_amax(am);
    if (lane == 0) d_xs[s] = am;
    float inv = QMAX / fmaxf(am, 1e-20f);
    #pragma unroll
    for (int t = 0; t < 6; t++) {
        int c = lane + 32 * t;
        int q1, q2; quant2(v[t], inv, q1, q2);
        d_xq1[(size_t)s * KQ1 + c] = (int8_t)q1;
        d_xq2[(size_t)s * KQ1 + c] = (int8_t)q2;
    }
}

__global__ void prep_w1q(const float* __restrict__ w1, const float* __restrict__ wma) {
    int o = blockIdx.x * 8 + (threadIdx.x >> 5);
    int lane = threadIdx.x & 31;
    if (o >= HID) return;
    float v[6];
    #pragma unroll
    for (int t = 0; t < 6; t++) {
        int c = lane + 32 * t;
        float val = 0.f;
        if (c < CIN)           val = w1[(size_t)o * CIN + c];
        else if (c < CIN + NC) val = wma[(size_t)o * NC + (c - CIN)];
        v[t] = val;
    }
    float am = 0.f;
    #pragma unroll
    for (int t = 0; t < 6; t++) am = fmaxf(am, fabsf(v[t]));
    am = warp_amax(am);
    if (lane == 0) d_w1s[o] = am;
    float inv = QMAX / fmaxf(am, 1e-20f);
    #pragma unroll
    for (int t = 0; t < 6; t++) {
        int c = lane + 32 * t;
        int q1, q2; quant2(v[t], inv, q1, q2);
        d_w1q1[(size_t)o * KQ1 + c] = (int8_t)q1;
        d_w1q2[(size_t)o * KQ1 + c] = (int8_t)q2;
    }
}

__global__ void prep_wmq(const float* __restrict__ mlw) {
    int r = blockIdx.x * 8 + (threadIdx.x >> 5);
    int lane = threadIdx.x & 31;
    if (r >= 5 * HID) return;
    int layer = r >> 8;
    float v[8];
    #pragma unroll
    for (int t = 0; t < 8; t++) {
        int k = lane + 32 * t;
        v[t] = mlw[(size_t)r * HID + k] * d_alpha[layer * HID + k];
    }
    float am = 0.f;
    #pragma unroll
    for (int t = 0; t < 8; t++) am = fmaxf(am, fabsf(v[t]));
    am = warp_amax(am);
    if (lane == 0) d_wms[r] = am;
    float inv = QMAX / fmaxf(am, 1e-20f);
    #pragma unroll
    for (int t = 0; t < 8; t++) {
        int k = lane + 32 * t;
        int q1, q2; quant2(v[t], inv, q1, q2);
        d_wmq1[(size_t)r * HID + k] = (int8_t)q1;
        d_wmq2[(size_t)r * HID + k] = (int8_t)q2;
    }
}

__global__ void prep_wcq(const float* __restrict__ wc) {
    int o = blockIdx.x * 8 + (threadIdx.x >> 5);
    int lane = threadIdx.x & 31;
    if (o >= COL) return;
    float v[8];
    #pragma unroll
    for (int t = 0; t < 8; t++) v[t] = wc[(size_t)o * HID + lane + 32 * t];
    float am = 0.f;
    #pragma unroll
    for (int t = 0; t < 8; t++) am = fmaxf(am, fabsf(v[t]));
    am = warp_amax(am);
    if (lane == 0) d_wcs[o] = am;
    float inv = QMAX / fmaxf(am, 1e-20f);
    #pragma unroll
    for (int t = 0; t < 8; t++) {
        int q1, q2; quant2(v[t], inv, q1, q2);
        d_wcq1[(size_t)o * HID + lane + 32 * t] = (int8_t)q1;
        d_wcq2[(size_t)o * HID + lane + 32 * t] = (int8_t)q2;
    }
}

__global__ void prep_twf(const float* __restrict__ w, float* __restrict__ out) {
    int idx = blockIdx.x * blockDim.x + threadIdx.x;
    if (idx >= 9 * HID * HID) return;
    int tap = idx / (HID * HID);
    int ok  = idx - tap * (HID * HID);
    out[idx] = w[(size_t)ok * 9 + tap];
}

__global__ void reset_amax() {
    int idx = blockIdx.x * blockDim.x + threadIdx.x;
    if (idx < 7 * HID) d_camax[idx] = 0.f;
}

// ---------------------------------------------------------------------------
// Fused activation-quant + weight-requant.
// ---------------------------------------------------------------------------
template<int C, int TAPS, int K>
__global__ void qa_wr(const __nv_bfloat16* __restrict__ hi,
                      const __nv_bfloat16* __restrict__ lo,
                      const float* __restrict__ camax,
                      int8_t* __restrict__ q1p, int8_t* __restrict__ q2p,
                      const float* __restrict__ wsrc,
                      int8_t* __restrict__ wq1, int8_t* __restrict__ wq2,
                      float* __restrict__ Ts, int nq) {
    if ((int)blockIdx.x < nq) {
        int idx = blockIdx.x * 256 + threadIdx.x;
        if (idx >= HWPIX * C) return;
        int c = idx & (C - 1);
        float v = __bfloat162float(hi[idx]) + __bfloat162float(lo[idx]);
        float inv = QMAX / fmaxf(camax[c], 1e-20f);
        int q1, q2; quant2(v, inv, q1, q2);
        q1p[idx] = (int8_t)q1;
        q2p[idx] = (int8_t)q2;
    } else {
        int o = (blockIdx.x - nq) * 8 + (threadIdx.x >> 5);
        int lane = threadIdx.x & 31;
        if (o >= HID) return;
        const int E = TAPS * K;
        float am = 0.f;
        for (int e = lane; e < E; e += 32) {
            int tap = e / K, k = e - tap * K;
            float u = wsrc[(size_t)tap * (HID * K) + (size_t)o * K + k] * camax[k];
            am = fmaxf(am, fabsf(u));
        }
        am = warp_amax(am);
        if (lane == 0) Ts[o] = am / QDEN;
        float inv = QMAX / fmaxf(am, 1e-20f);
        for (int e = lane; e < E; e += 32) {
            int tap = e / K, k = e - tap * K;
            size_t idx = (size_t)tap * (HID * K) + (size_t)o * K + k;
            float u = wsrc[idx] * camax[k];
            int q1, q2; quant2(u, inv, q1, q2);
            wq1[idx] = (int8_t)q1;
            wq2[idx] = (int8_t)q2;
        }
    }
}

// ---------------------------------------------------------------------------
// MLP int8 GEMM, B-resident; 2 K-chunks per barrier, 3 rotating A buffers.
// 512 threads; WN=8, WM=2, MI=2; CTA owns MT*MTILES rows.
// ---------------------------------------------------------------------------
template<int NTHR, int MT, int MTILES, int NT, int K, bool LRELU_, bool QOUT>
__global__ void __launch_bounds__(NTHR)
imma_brg(const int8_t* __restrict__ Aq1, const int8_t* __restrict__ Aq2,
         const float* __restrict__ As,
         const int8_t* __restrict__ Bq1, const int8_t* __restrict__ Bq2,
         const float* __restrict__ Bs,
         const float* __restrict__ bias,
         int8_t* __restrict__ Oq1, int8_t* __restrict__ Oq2, float* __restrict__ Os,
         float* __restrict__ Of, int OC) {
    extern __shared__ char smem[];
    constexpr int NCH  = K / 64;
    constexpr int NHALF = (NCH + 1) / 2;
    constexpr int NGI2 = MTILES * NHALF;
    constexpr int BSL  = NT * 80;
    constexpr int ASL  = MT * 80;
    constexpr int CSL  = 2 * ASL;            // one chunk, both planes
    constexpr int ABUF = 2 * CSL;            // one buffer holds 2 chunks
    constexpr int B2OFF = NCH * BSL;
    constexpr int AO   = 2 * NCH * BSL;
    constexpr int SFO  = AO + 3 * ABUF;
    constexpr int NW   = NTHR / 32;
    constexpr int WN   = NT / 32;
    constexpr int WM   = NW / WN;
    constexpr int MI   = MT / (16 * WM);

    const uint32_t sb = smem_u32(smem);
    const int tid = threadIdx.x;
    const int lane = tid & 31, wid = tid >> 5;
    const int wn = wid % WN, wm = wid / WN;
    const int g = lane >> 2, q = lane & 3;
    const int rbase0 = blockIdx.x * (MT * MTILES);

    // ---- B: all chunks, both planes, once ----
    for (int idx = tid; idx < NCH * NT * 4; idx += NTHR) {
        const int ch = idx / (NT * 4);
        const int rem = idx - ch * (NT * 4);
        const int row = rem >> 2, cc = rem & 3;
        const size_t go = (size_t)row * K + ch * 64 + cc * 16;
        const uint32_t d = sb + ch * BSL + row * 80 + cc * 16;
        cpa16z(d,         Bq1 + go, 16);
        cpa16z(d + B2OFF, Bq2 + go, 16);
    }
    auto load_A2 = [&](int bufi, int gi2) {
        const int mt = gi2 / NHALF, h = gi2 - mt * NHALF;
        const int ncc = (2 * h + 2 <= NCH) ? 2 : 1;
        for (int idx = tid; idx < ncc * MT * 4; idx += NTHR) {
            const int ci = idx / (MT * 4);
            const int rem = idx - ci * (MT * 4);
            const int row = rem >> 2, cc4 = rem & 3;
            const int c = 2 * h + ci;
            const size_t go = (size_t)(rbase0 + mt * MT + row) * K + c * 64 + cc4 * 16;
            const uint32_t d = sb + AO + bufi * ABUF + ci * CSL + row * 80 + cc4 * 16;
            cpa16z(d,       Aq1 + go, 16);
            cpa16z(d + ASL, Aq2 + go, 16);
        }
    };
    load_A2(0, 0);
    asm volatile("cp.async.commit_group;" ::: "memory");

    int acc1[MI][4][4], acc2[MI][4][4];
    #pragma unroll
    for (int i = 0; i < MI; i++)
        #pragma unroll
        for (int j = 0; j < 4; j++)
            #pragma unroll
            for (int r = 0; r < 4; r++) { acc1[i][j][r] = 0; acc2[i][j][r] = 0; }

    float* sf = reinterpret_cast<float*>(smem + SFO);
    int buf = 0, nbuf = 1;

    for (int gi2 = 0; gi2 < NGI2; gi2++) {
        if (gi2 + 1 < NGI2) {
            load_A2(nbuf, gi2 + 1);
            asm volatile("cp.async.commit_group;" ::: "memory");
            asm volatile("cp.async.wait_group 1;" ::: "memory");
        } else {
            asm volatile("cp.async.wait_group 0;" ::: "memory");
        }
        __syncthreads();
        const int mt = gi2 / NHALF, h = gi2 - mt * NHALF;
        const int ncc = (2 * h + 2 <= NCH) ? 2 : 1;
        for (int ci = 0; ci < ncc; ci++) {
            const int c = 2 * h + ci;
            const uint32_t Ab = sb + AO + buf * ABUF + ci * CSL;
            const uint32_t Bb = sb + c * BSL;
            #pragma unroll
            for (int kk = 0; kk < 2; kk++) {
                const int koff = kk * 32;
                uint32_t a1[MI][4], a2[MI][4];
                #pragma unroll
                for (int i = 0; i < MI; i++) {
                    const uint32_t r0 = ldm_a_addr(Ab + (uint32_t)(wm * MI * 16 + i * 16) * 80 + koff, lane);
                    ldm_x4(a1[i], r0);
                    ldm_x4(a2[i], r0 + ASL);
                }
                uint32_t b1[4][2], b2[4][2];
                #pragma unroll
                for (int jp = 0; jp < 2; jp++) {
                    const uint32_t r0 = ldm_b_addr(Bb + (uint32_t)(wn * 32 + jp * 16) * 80 + koff, lane);
                    uint32_t t[4];
                    ldm_x4(t, r0);
                    b1[2 * jp][0] = t[0]; b1[2 * jp][1] = t[1];
                    b1[2 * jp + 1][0] = t[2]; b1[2 * jp + 1][1] = t[3];
                    ldm_x4(t, r0 + B2OFF);
                    b2[2 * jp][0] = t[0]; b2[2 * jp][1] = t[1];
                    b2[2 * jp + 1][0] = t[2]; b2[2 * jp + 1][1] = t[3];
                }
                #pragma unroll
                for (int i = 0; i < MI; i++)
                    #pragma unroll
                    for (int j = 0; j < 4; j++) {
                        imma16832(acc1[i][j], a1[i], b1[j]);
                        imma16832(acc2[i][j], a1[i], b2[j]);
                        imma16832(acc2[i][j], a2[i], b1[j]);
                    }
            }
        }
        buf = nbuf; nbuf = (nbuf == 2) ? 0 : nbuf + 1;

        if (h == NHALF - 1) {
            // ---- epilogue for m-tile mt ----
            const int rbase = rbase0 + mt * MT;
            if (QOUT) {
                for (int i2 = tid; i2 < MT; i2 += NTHR) sf[i2] = 0.f;
                __syncthreads();
            }
            float sbv[4][2], bv[4][2];
            #pragma unroll
            for (int j = 0; j < 4; j++) {
                const int col0 = wn * 32 + j * 8 + q * 2;
                sbv[j][0] = Bs[col0];     sbv[j][1] = Bs[col0 + 1];
                bv[j][0]  = bias[col0];   bv[j][1]  = bias[col0 + 1];
            }
            #pragma unroll
            for (int i = 0; i < MI; i++) {
                #pragma unroll
                for (int h2 = 0; h2 < 2; h2++) {
                    const int lrow = wm * MI * 16 + i * 16 + g + h2 * 8;
                    const float sa = As[rbase + lrow] * (1.f / QDEN);
                    float rmax = 0.f;
                    #pragma unroll
                    for (int j = 0; j < 4; j++) {
                        float t0 = 16384.f * (float)acc1[i][j][h2 * 2 + 0] + 128.f * (float)acc2[i][j][h2 * 2 + 0];
                        float t1 = 16384.f * (float)acc1[i][j][h2 * 2 + 1] + 128.f * (float)acc2[i][j][h2 * 2 + 1];
                        float v0 = sa * sbv[j][0] * t0 + bv[j][0];
                        float v1 = sa * sbv[j][1] * t1 + bv[j][1];
                        if (LRELU_) { v0 = lrelu(v0); v1 = lrelu(v1); }
                        acc1[i][j][h2 * 2 + 0] = __float_as_int(v0);
                        acc1[i][j][h2 * 2 + 1] = __float_as_int(v1);
                        rmax = fmaxf(rmax, fmaxf(fabsf(v0), fabsf(v1)));
                    }
                    if (QOUT) {
                        rmax = fmaxf(rmax, __shfl_xor_sync(0xFFFFFFFFu, rmax, 1));
                        rmax = fmaxf(rmax, __shfl_xor_sync(0xFFFFFFFFu, rmax, 2));
                        if (q == 0) amax_atomic(&sf[lrow], rmax);
                    }
                }
            }
            if (QOUT) {
                __syncthreads();
                #pragma unroll
                for (int i = 0; i < MI; i++) {
                    #pragma unroll
                    for (int h2 = 0; h2 < 2; h2++) {
                        const int lrow = wm * MI * 16 + i * 16 + g + h2 * 8;
                        const int grow = rbase + lrow;
                        const float mx = sf[lrow];
                        const float inv = QMAX / fmaxf(mx, 1e-20f);
                        if (wn == 0 && q == 0) Os[grow] = mx;
                        #pragma unroll
                        for (int j = 0; j < 4; j++) {
                            const int col0 = wn * 32 + j * 8 + q * 2;
                            float v0 = __int_as_float(acc1[i][j][h2 * 2 + 0]);
                            float v1 = __int_as_float(acc1[i][j][h2 * 2 + 1]);
                            int p1, p2, r1, r2;
                            quant2(v0, inv, p1, p2);
                            quant2(v1, inv, r1, r2);
                            char2 o1; o1.x = (char)p1; o1.y = (char)r1;
                            char2 o2; o2.x = (char)p2; o2.y = (char)r2;
                            *reinterpret_cast<char2*>(Oq1 + (size_t)grow * OC + col0) = o1;
                            *reinterpret_cast<char2*>(Oq2 + (size_t)grow * OC + col0) = o2;
                        }
                    }
                }
                __syncthreads();
            } else {
                #pragma unroll
                for (int i = 0; i < MI; i++) {
                    #pragma unroll
                    for (int h2 = 0; h2 < 2; h2++) {
                        const int lrow = wm * MI * 16 + i * 16 + g + h2 * 8;
                        const int grow = rbase + lrow;
                        #pragma unroll
                        for (int j = 0; j < 4; j++) {
                            const int col0 = wn * 32 + j * 8 + q * 2;
                            float2 v;
                            v.x = __int_as_float(acc1[i][j][h2 * 2 + 0]);
                            v.y = __int_as_float(acc1[i][j][h2 * 2 + 1]);
                            *reinterpret_cast<float2*>(Of + (size_t)grow * OC + col0) = v;
                        }
                    }
                }
            }
            #pragma unroll
            for (int i = 0; i < MI; i++)
                #pragma unroll
                for (int j = 0; j < 4; j++)
                    #pragma unroll
                    for (int r = 0; r < 4; r++) { acc1[i][j][r] = 0; acc2[i][j][r] = 0; }
        }
    }
}

// ---------------------------------------------------------------------------
// Fused wc head + compositing
// ---------------------------------------------------------------------------
__global__ void __launch_bounds__(256)
lwcomp(const int8_t* __restrict__ Aq1, const int8_t* __restrict__ Aq2,
       const float* __restrict__ As,
       const int8_t* __restrict__ Bq1, const int8_t* __restrict__ Bq2,
       const float* __restrict__ Bs, const float* __restrict__ bias,
       const float* __restrict__ sigma, const float* __restrict__ dists,
       __nv_bfloat16* __restrict__ feath, __nv_bfloat16* __restrict__ featl,
       float* __restrict__ amax_out) {
    extern __shared__ char smem[];
    constexpr int MT = 128, NT = 64, K = HID;
    constexpr int NCH   = K / 64;
    constexpr int ASLAB = MT * 80;
    constexpr int BSLAB = NT * 80;
    constexpr int BOFF  = 2 * ASLAB;
    constexpr int BUF   = 2 * ASLAB + 2 * BSLAB;
    constexpr int WN = 2, WM = 4, MI = 2;
    constexpr int TSTR = 68;

    const uint32_t sb = smem_u32(smem);
    const int tid = threadIdx.x;
    const int lane = tid & 31, wid = tid >> 5;
    const int wn = wid % WN, wm = wid / WN;
    const int g = lane >> 2, q = lane & 3;
    const int rbase = blockIdx.x * MT;
    const int pb = blockIdx.x * 8;

    auto load_chunk = [&](int bufi, int c) {
        const uint32_t base = sb + bufi * BUF;
        const int k0 = c * 64;
        for (int idx = tid; idx < MT * 4; idx += 256) {
            const int row = idx >> 2, cc = idx & 3;
            const size_t go = (size_t)(rbase + row) * K + k0 + cc * 16;
            const uint32_t d = base + row * 80 + cc * 16;
            cpa16z(d,         Aq1 + go, 16);
            cpa16z(d + ASLAB, Aq2 + go, 16);
        }
        for (int idx = tid; idx < NT * 4; idx += 256) {
            const int row = idx >> 2, cc = idx & 3;
            const size_t go = (size_t)row * K + k0 + cc * 16;
            const uint32_t d = base + BOFF + row * 80 + cc * 16;
            cpa16z(d,         Bq1 + go, 16);
            cpa16z(d + BSLAB, Bq2 + go, 16);
        }
        asm volatile("cp.async.commit_group;" ::: "memory");
    };

    int acc1[MI][4][4], acc2[MI][4][4];
    #pragma unroll
    for (int i = 0; i < MI; i++)
        #pragma unroll
        for (int j = 0; j < 4; j++)
            #pragma unroll
            for (int r = 0; r < 4; r++) { acc1[i][j][r] = 0; acc2[i][j][r] = 0; }

    load_chunk(0, 0);
    int buf = 0, nbuf = 1;
    for (int c = 0; c < NCH; c++) {
        if (c + 1 < NCH) {
            load_chunk(nbuf, c + 1);
            asm volatile("cp.async.wait_group 1;" ::: "memory");
        } else {
            asm volatile("cp.async.wait_group 0;" ::: "memory");
        }
        __syncthreads();
        const uint32_t Ab = sb + buf * BUF;
        const uint32_t Bb = Ab + BOFF;
        #pragma unroll
        for (int kk = 0; kk < 2; kk++) {
            const int koff = kk * 32;
            uint32_t a1[MI][4], a2[MI][4];
            #pragma unroll
            for (int i = 0; i < MI; i++) {
                const uint32_t r0 = ldm_a_addr(Ab + (uint32_t)(wm * MI * 16 + i * 16) * 80 + koff, lane);
                ldm_x4(a1[i], r0);
                ldm_x4(a2[i], r0 + ASLAB);
            }
            uint32_t b1[4][2], b2[4][2];
            #pragma unroll
            for (int jp = 0; jp < 2; jp++) {
                const uint32_t r0 = ldm_b_addr(Bb + (uint32_t)(wn * 32 + jp * 16) * 80 + koff, lane);
                uint32_t t[4];
                ldm_x4(t, r0);
                b1[2 * jp][0] = t[0]; b1[2 * jp][1] = t[1];
                b1[2 * jp + 1][0] = t[2]; b1[2 * jp + 1][1] = t[3];
                ldm_x4(t, r0 + BSLAB);
                b2[2 * jp][0] = t[0]; b2[2 * jp][1] = t[1];
                b2[2 * jp + 1][0] = t[2]; b2[2 * jp + 1][1] = t[3];
            }
            #pragma unroll
            for (int i = 0; i < MI; i++)
                #pragma unroll
                for (int j = 0; j < 4; j++) {
                    imma16832(acc1[i][j], a1[i], b1[j]);
                    imma16832(acc2[i][j], a1[i], b2[j]);
                    imma16832(acc2[i][j], a2[i], b1[j]);
                }
        }
        buf = nbuf; nbuf = (nbuf == 2) ? 0 : nbuf + 1;
    }
    __syncthreads();

    float* tile = reinterpret_cast<float*>(smem);
    float* wg   = reinterpret_cast<float*>(smem) + MT * TSTR;
    float* sch  = wg + 8 * MM;
    #pragma unroll
    for (int j = 0; j < 4; j++) {
        const int col0 = wn * 32 + j * 8 + q * 2;
        const float sb0 = Bs[col0], sb1 = Bs[col0 + 1];
        const float b0 = bias[col0], b1 = bias[col0 + 1];
        #pragma unroll
        for (int i = 0; i < MI; i++) {
            #pragma unroll
            for (int h = 0; h < 2; h++) {
                const int lrow = wm * MI * 16 + i * 16 + g + h * 8;
                const float sa = As[rbase + lrow] * (1.f / QDEN);
                float t0 = 16384.f * (float)acc1[i][j][h * 2 + 0] + 128.f * (float)acc2[i][j][h * 2 + 0];
                float t1 = 16384.f * (float)acc1[i][j][h * 2 + 1] + 128.f * (float)acc2[i][j][h * 2 + 1];
                float2 v;
                v.x = sa * sb0 * t0 + b0;
                v.y = sa * sb1 * t1 + b1;
                *reinterpret_cast<float2*>(&tile[lrow * TSTR + col0]) = v;
            }
        }
    }
    if (tid < 8) {
        const int pix = pb + tid;
        float T = 1.f;
        #pragma unroll
        for (int m2 = 0; m2 < MM; m2++) {
            float sg = sigma[pix * MM + m2];
            sg = sg > 0.f ? sg : 0.f;
            float a = 1.f - expf(-sg * dists[pix * MM + m2]);
            wg[tid * MM + m2] = a * T;
            T *= (1.f - a + 1e-10f);
        }
    }
    if (tid >= 64 && tid < 128) sch[tid - 64] = 0.f;
    __syncthreads();

    const int c0 = tid & 63;
    float lm = 0.f;
    #pragma unroll
    for (int t2 = 0; t2 < 2; t2++) {
        const int o = tid + t2 * 256;
        const int pix = o >> 6;
        float acc = 0.f;
        #pragma unroll
        for (int m2 = 0; m2 < MM; m2++)
            acc += wg[pix * MM + m2] * tile[(pix * MM + m2) * TSTR + c0];
        __nv_bfloat16 hbf = __float2bfloat16(acc);
        feath[(size_t)(pb + pix) * COL + c0] = hbf;
        featl[(size_t)(pb + pix) * COL + c0] = __float2bfloat16(acc - __bfloat162float(hbf));
        lm = fmaxf(lm, fabsf(acc));
    }
    amax_atomic(&sch[c0], lm);
    __syncthreads();
    if (tid < 64) amax_atomic(&amax_out[tid], sch[tid]);
}

// ---------------------------------------------------------------------------
// CNN int8 conv: 256 threads, tile 64 px x 128 ch, triple-buffered.
// ---------------------------------------------------------------------------
template<int TAPS, int K, bool HAS_BIAS, bool HAS_RES, bool HAS_MOD, bool DO_AMAX>
__global__ void __launch_bounds__(256)
conv_q(const int8_t* __restrict__ Aq1, const int8_t* __restrict__ Aq2,
       const int8_t* __restrict__ Wq1, const int8_t* __restrict__ Wq2,
       const float* __restrict__ Ts, const float* __restrict__ bias,
       const __nv_bfloat16* __restrict__ ResH, const __nv_bfloat16* __restrict__ ResL,
       const float* __restrict__ zc, int modoff,
       __nv_bfloat16* __restrict__ Chi, __nv_bfloat16* __restrict__ Clo,
       float* __restrict__ amax_out) {
    extern __shared__ char smem[];
    constexpr int KCH    = K / 64;
    constexpr int NCHUNK = TAPS * KCH;
    constexpr int ASLAB  = 64 * 80;
    constexpr int BSLAB  = 128 * 80;
    constexpr int BOFF   = 2 * ASLAB;
    constexpr int BUF    = 2 * ASLAB + 2 * BSLAB;
    constexpr int MI     = 2;

    const uint32_t sb = smem_u32(smem);
    const int tid = threadIdx.x;
    const int lane = tid & 31, wid = tid >> 5;
    const int wn = wid & 3, wm = wid >> 2;
    const int g = lane >> 2, q = lane & 3;
    const int o0 = blockIdx.y * 128;
    const int py0 = (int)blockIdx.x >> 1;
    const int px0 = ((int)blockIdx.x & 1) << 6;

    auto load_chunk = [&](int bufi, int chunk) {
        const int tap = (TAPS == 9) ? (chunk / KCH) : 0;
        const int k0  = ((TAPS == 9) ? (chunk - tap * KCH) : chunk) * 64;
        const uint32_t base = sb + bufi * BUF;
        {
            const int row = tid >> 2, cc = tid & 3;
            uint32_t sz = 16;
            int pix;
            if (TAPS == 9) {
                const int dy = tap / 3 - 1, dx = tap % 3 - 1;
                const int py = py0 + dy, px = px0 + row + dx;
                const bool ok = (py >= 0) && (py < HH) && (px >= 0) && (px < WW);
                sz = ok ? 16u : 0u;
                pix = ok ? (py * WW + px) : 0;
            } else {
                pix = py0 * WW + px0 + row;
            }
            const size_t go = (size_t)pix * K + k0 + cc * 16;
            const uint32_t d = base + row * 80 + cc * 16;
            cpa16z(d,         Aq1 + go, sz);
            cpa16z(d + ASLAB, Aq2 + go, sz);
        }
        for (int idx = tid; idx < 128 * 4; idx += 256) {
            const int row = idx >> 2, cc = idx & 3;
            const size_t go = (size_t)tap * (HID * K) + (size_t)(o0 + row) * K + k0 + cc * 16;
            const uint32_t d = base + BOFF + row * 80 + cc * 16;
            cpa16z(d,         Wq1 + go, 16);
            cpa16z(d + BSLAB, Wq2 + go, 16);
        }
        asm volatile("cp.async.commit_group;" ::: "memory");
    };

    int acc1[MI][4][4], acc2[MI][4][4];
    #pragma unroll
    for (int i = 0; i < MI; i++)
        #pragma unroll
        for (int j = 0; j < 4; j++)
            #pragma unroll
            for (int r = 0; r < 4; r++) { acc1[i][j][r] = 0; acc2[i][j][r] = 0; }

    load_chunk(0, 0);
    int buf = 0, nbuf = 1;
    for (int c = 0; c < NCHUNK; c++) {
        if (c + 1 < NCHUNK) {
            load_chunk(nbuf, c + 1);
            asm volatile("cp.async.wait_group 1;" ::: "memory");
        } else {
            asm volatile("cp.async.wait_group 0;" ::: "memory");
        }
        __syncthreads();
        const uint32_t Ab = sb + buf * BUF;
        const uint32_t Bb = Ab + BOFF;
        #pragma unroll
        for (int kk = 0; kk < 2; kk++) {
            const int koff = kk * 32;
            uint32_t a1[MI][4], a2[MI][4];
            #pragma unroll
            for (int i = 0; i < MI; i++) {
                const uint32_t r0 = ldm_a_addr(Ab + (uint32_t)(wm * 32 + i * 16) * 80 + koff, lane);
                ldm_x4(a1[i], r0);
                ldm_x4(a2[i], r0 + ASLAB);
            }
            uint32_t b1[4][2], b2[4][2];
            #pragma unroll
            for (int jp = 0; jp < 2; jp++) {
                const uint32_t r0 = ldm_b_addr(Bb + (uint32_t)(wn * 32 + jp * 16) * 80 + koff, lane);
                uint32_t t[4];
                ldm_x4(t, r0);
                b1[2 * jp][0] = t[0]; b1[2 * jp][1] = t[1];
                b1[2 * jp + 1][0] = t[2]; b1[2 * jp + 1][1] = t[3];
                ldm_x4(t, r0 + BSLAB);
                b2[2 * jp][0] = t[0]; b2[2 * jp][1] = t[1];
                b2[2 * jp + 1][0] = t[2]; b2[2 * jp + 1][1] = t[3];
            }
            #pragma unroll
            for (int i = 0; i < MI; i++)
                #pragma unroll
                for (int j = 0; j < 4; j++) {
                    imma16832(acc1[i][j], a1[i], b1[j]);
                    imma16832(acc2[i][j], a1[i], b2[j]);
                    imma16832(acc2[i][j], a2[i], b1[j]);
                }
        }
        buf = nbuf; nbuf = (nbuf == 2) ? 0 : nbuf + 1;
    }

    __syncthreads();
    float* sch = reinterpret_cast<float*>(smem);
    if (DO_AMAX) {
        if (tid < 128) sch[tid] = 0.f;
        __syncthreads();
    }
    #pragma unroll
    for (int j = 0; j < 4; j++) {
        const int cl = wn * 32 + j * 8 + q * 2;
        const int colg = o0 + cl;
        const float t0 = Ts[colg], t1 = Ts[colg + 1];
        const float b0 = HAS_BIAS ? bias[colg]     : 0.f;
        const float b1 = HAS_BIAS ? bias[colg + 1] : 0.f;
        float sc0 = 1.f, sc1 = 1.f, sh0 = 0.f, sh1 = 0.f;
        if (HAS_MOD) {
            sc0 = zc[modoff + colg] + 1.f;       sc1 = zc[modoff + colg + 1] + 1.f;
            sh0 = zc[modoff + HID + colg];       sh1 = zc[modoff + HID + colg + 1];
        }
        float lm0 = 0.f, lm1 = 0.f;
        #pragma unroll
        for (int i = 0; i < MI; i++) {
            #pragma unroll
            for (int h = 0; h < 2; h++) {
                const int pix = py0 * WW + px0 + wm * 32 + i * 16 + g + h * 8;
                float v0 = t0 * (16384.f * (float)acc1[i][j][h * 2 + 0] + 128.f * (float)acc2[i][j][h * 2 + 0]) + b0;
                float v1 = t1 * (16384.f * (float)acc1[i][j][h * 2 + 1] + 128.f * (float)acc2[i][j][h * 2 + 1]) + b1;
                if (HAS_RES) {
                    __nv_bfloat162 rh = *reinterpret_cast<const __nv_bfloat162*>(ResH + (size_t)pix * HID + colg);
                    __nv_bfloat162 rl = *reinterpret_cast<const __nv_bfloat162*>(ResL + (size_t)pix * HID + colg);
                    v0 += __bfloat162float(rh.x) + __bfloat162float(rl.x);
                    v1 += __bfloat162float(rh.y) + __bfloat162float(rl.y);
                }
                if (HAS_MOD) { v0 = v0 * sc0 + sh0; v1 = v1 * sc1 + sh1; }
                v0 = lrelu(v0); v1 = lrelu(v1);
                if (DO_AMAX) { lm0 = fmaxf(lm0, fabsf(v0)); lm1 = fmaxf(lm1, fabsf(v1)); }
                __nv_bfloat162 hp = __floats2bfloat162_rn(v0, v1);
                float r0 = v0 - __bfloat162float(hp.x);
                float r1 = v1 - __bfloat162float(hp.y);
                __nv_bfloat162 lp = __floats2bfloat162_rn(r0, r1);
                *reinterpret_cast<__nv_bfloat162*>(Chi + (size_t)pix * HID + colg) = hp;
                *reinterpret_cast<__nv_bfloat162*>(Clo + (size_t)pix * HID + colg) = lp;
            }
        }
        if (DO_AMAX) {
            #pragma unroll
            for (int off = 4; off <= 16; off <<= 1) {
                lm0 = fmaxf(lm0, __shfl_xor_sync(0xFFFFFFFFu, lm0, off));
                lm1 = fmaxf(lm1, __shfl_xor_sync(0xFFFFFFFFu, lm1, off));
            }
            if (g == 0) {
                amax_atomic(&sch[cl], lm0);
                amax_atomic(&sch[cl + 1], lm1);
            }
        }
    }
    if (DO_AMAX) {
        __syncthreads();
        if (tid < 128) amax_atomic(&amax_out[o0 + tid], sch[tid]);
    }
}

// ---------------------------------------------------------------------------
// sigma (warp per sample)
// ---------------------------------------------------------------------------
__global__ void sigma_q(const int8_t* __restrict__ A1, const int8_t* __restrict__ A2,
                        const float* __restrict__ As, const float* __restrict__ wsig,
                        const float* __restrict__ bsig, float* __restrict__ out) {
    int s = (blockIdx.x * blockDim.x + threadIdx.x) >> 5;
    int lane = threadIdx.x & 31;
    if (s >= S_TOT) return;
    const char4* p1 = reinterpret_cast<const char4*>(A1 + (size_t)s * HID);
    const char4* p2 = reinterpret_cast<const char4*>(A2 + (size_t)s * HID);
    float acc = 0.f;
    #pragma unroll
    for (int t = 0; t < 2; t++) {
        int idx = lane + 32 * t;
        char4 c1 = p1[idx];
        char4 c2 = p2[idx];
        int k = idx * 4;
        acc += (float)(c1.x * 128 + c2.x) * wsig[k + 0];
        acc += (float)(c1.y * 128 + c2.y) * wsig[k + 1];
        acc += (float)(c1.z * 128 + c2.z) * wsig[k + 2];
        acc += (float)(c1.w * 128 + c2.w) * wsig[k + 3];
    }
    #pragma unroll
    for (int off = 16; off; off >>= 1) acc += __shfl_xor_sync(0xFFFFFFFFu, acc, off);
    if (lane == 0) out[s] = acc * (As[s] * (1.f / QMAX)) + bsig[0];
}

// ---------------------------------------------------------------------------
// Final 1x1 conv to 3 channels (warp per pixel)
// ---------------------------------------------------------------------------
__global__ void final_conv(const __nv_bfloat16* __restrict__ InH,
                           const __nv_bfloat16* __restrict__ InL,
                           const float* __restrict__ w,
                           const float* __restrict__ b, float* __restrict__ out) {
    int warp = (blockIdx.x * blockDim.x + threadIdx.x) >> 5;
    int lane = threadIdx.x & 31;
    if (warp >= HWPIX) return;
    const __nv_bfloat16* ph = InH + (size_t)warp * HID;
    const __nv_bfloat16* pl = InL + (size_t)warp * HID;
    float a0 = 0.f, a1 = 0.f, a2 = 0.f;
    #pragma unroll
    for (int t = 0; t < 8; t++) {
        int i = lane + 32 * t;
        float v = __bfloat162float(ph[i]) + __bfloat162float(pl[i]);
        a0 += v * w[i];
        a1 += v * w[HID + i];
        a2 += v * w[2 * HID + i];
    }
    #pragma unroll
    for (int off = 16; off; off >>= 1) {
        a0 += __shfl_xor_sync(0xFFFFFFFFu, a0, off);
        a1 += __shfl_xor_sync(0xFFFFFFFFu, a1, off);
        a2 += __shfl_xor_sync(0xFFFFFFFFu, a2, off);
    }
    if (lane == 0) {
        out[warp]             = a0 + b[0];
        out[HWPIX + warp]     = a1 + b[1];
        out[2 * HWPIX + warp] = a2 + b[2];
    }
}

// ---------------------------------------------------------------------------
// Launch
// ---------------------------------------------------------------------------
extern "C" void kernel_launch(void* const* d_in, const int* in_sizes, int n_in,
                              void* d_out, int out_size) {
    const float* x     = (const float*)d_in[0];
    const float* m     = (const float*)d_in[1];
    const float* z     = (const float*)d_in[2];
    const float* dists = (const float*)d_in[3];
    const float* w1    = (const float*)d_in[4];
    const float* b1    = (const float*)d_in[5];
    const float* wma   = (const float*)d_in[6];
    const float* ml_w  = (const float*)d_in[7];
    const float* ml_wa = (const float*)d_in[8];
    const float* ml_ba = (const float*)d_in[9];
    const float* ml_wb = (const float*)d_in[10];
    const float* ml_bb = (const float*)d_in[11];
    const float* wsig  = (const float*)d_in[12];
    const float* bsig  = (const float*)d_in[13];
    const float* wc    = (const float*)d_in[14];
    const float* bc    = (const float*)d_in[15];
    const float* wz    = (const float*)d_in[16];
    const float* bz    = (const float*)d_in[17];
    const float* c1_w  = (const float*)d_in[18];
    const float* c1_b  = (const float*)d_in[19];
    const float* c2a_w = (const float*)d_in[20];
    const float* c2a_b = (const float*)d_in[21];
    const float* c2b_w = (const float*)d_in[22];
    const float* c3a_w = (const float*)d_in[23];
    const float* c3a_b = (const float*)d_in[24];
    const float* c3b_w = (const float*)d_in[25];
    const float* c4a_w = (const float*)d_in[26];
    const float* c4a_b = (const float*)d_in[27];
    const float* c4b_w = (const float*)d_in[28];
    const float* c4b_b = (const float*)d_in[29];
    const float* c4_w  = (const float*)d_in[30];
    const float* c4_b  = (const float*)d_in[31];
    float* out = (float*)d_out;

    int8_t *xq1, *xq2, *aq1, *aq2, *bq1, *bq2;
    int8_t *w1q1, *w1q2, *wmq1, *wmq2, *wcq1, *wcq2, *cq1, *cq2, *cwq1, *cwq2;
    float *xs, *as, *bsc, *w1s, *wms, *wcs, *wt3f, *cts, *camax;
    __nv_bfloat16 *yah, *yal, *ybh, *ybl, *ych, *ycl, *fth, *ftl;
    float *sig, *zcv, *be;
    cudaGetSymbolAddress((void**)&xq1, d_xq1);
    cudaGetSymbolAddress((void**)&xq2, d_xq2);
    cudaGetSymbolAddress((void**)&xs,  d_xs);
    cudaGetSymbolAddress((void**)&aq1, d_aq1);
    cudaGetSymbolAddress((void**)&aq2, d_aq2);
    cudaGetSymbolAddress((void**)&as,  d_as);
    cudaGetSymbolAddress((void**)&bq1, d_bq1);
    cudaGetSymbolAddress((void**)&bq2, d_bq2);
    cudaGetSymbolAddress((void**)&bsc, d_bsc);
    cudaGetSymbolAddress((void**)&w1q1, d_w1q1);
    cudaGetSymbolAddress((void**)&w1q2, d_w1q2);
    cudaGetSymbolAddress((void**)&w1s,  d_w1s);
    cudaGetSymbolAddress((void**)&wmq1, d_wmq1);
    cudaGetSymbolAddress((void**)&wmq2, d_wmq2);
    cudaGetSymbolAddress((void**)&wms,  d_wms);
    cudaGetSymbolAddress((void**)&wcq1, d_wcq1);
    cudaGetSymbolAddress((void**)&wcq2, d_wcq2);
    cudaGetSymbolAddress((void**)&wcs,  d_wcs);
    cudaGetSymbolAddress((void**)&wt3f, d_wt3f);
    cudaGetSymbolAddress((void**)&cwq1, d_cwq1);
    cudaGetSymbolAddress((void**)&cwq2, d_cwq2);
    cudaGetSymbolAddress((void**)&cts,  d_cts);
    cudaGetSymbolAddress((void**)&camax, d_camax);
    cudaGetSymbolAddress((void**)&cq1, d_cq1);
    cudaGetSymbolAddress((void**)&cq2, d_cq2);
    cudaGetSymbolAddress((void**)&yah, d_yah);
    cudaGetSymbolAddress((void**)&yal, d_yal);
    cudaGetSymbolAddress((void**)&ybh, d_ybh);
    cudaGetSymbolAddress((void**)&ybl, d_ybl);
    cudaGetSymbolAddress((void**)&ych, d_ych);
    cudaGetSymbolAddress((void**)&ycl, d_ycl);
    cudaGetSymbolAddress((void**)&fth, d_feath);
    cudaGetSymbolAddress((void**)&ftl, d_featl);
    cudaGetSymbolAddress((void**)&sig, d_sig);
    cudaGetSymbolAddress((void**)&zcv, d_zc);
    cudaGetSymbolAddress((void**)&be,  d_beta);

    const int TWF = 9 * HID * HID;
    const int SM_L1 = 2 * 3 * (256 * 80) + 3 * (2 * 2 * 64 * 80) + 256;   // 184576
    const int SM_LH = 2 * 4 * (256 * 80) + 3 * (2 * 2 * 64 * 80) + 256;   // 225536
    const int SM_LC = 3 * (2 * 128 * 80 + 2 * 64 * 80);                    // 92160
    const int SMCV  = 3 * (2 * 64 * 80 + 2 * 128 * 80);                    // 92160

    auto L1 = imma_brg<512, 64, 4, 256, KQ1, true, true>;
    auto LH = imma_brg<512, 64, 4, 256, HID, true, true>;
    auto CV1  = conv_q<1, COL, true,  false, false, true >;
    auto CVA  = conv_q<9, HID, true,  false, false, true >;
    auto CVB  = conv_q<9, HID, false, true,  true,  true >;
    auto CV4A = conv_q<1, HID, true,  false, false, true >;
    auto CV4B = conv_q<1, HID, true,  true,  false, false>;

    cudaFuncSetAttribute(L1,     cudaFuncAttributeMaxDynamicSharedMemorySize, SM_L1);
    cudaFuncSetAttribute(LH,     cudaFuncAttributeMaxDynamicSharedMemorySize, SM_LH);
    cudaFuncSetAttribute(lwcomp, cudaFuncAttributeMaxDynamicSharedMemorySize, SM_LC);
    cudaFuncSetAttribute(CV1,  cudaFuncAttributeMaxDynamicSharedMemorySize, SMCV);
    cudaFuncSetAttribute(CVA,  cudaFuncAttributeMaxDynamicSharedMemorySize, SMCV);
    cudaFuncSetAttribute(CVB,  cudaFuncAttributeMaxDynamicSharedMemorySize, SMCV);
    cudaFuncSetAttribute(CV4A, cudaFuncAttributeMaxDynamicSharedMemorySize, SMCV);
    cudaFuncSetAttribute(CV4B, cudaFuncAttributeMaxDynamicSharedMemorySize, SMCV);

    const int GRB = S_TOT / 256;   // 1024 (64 rows x 4 m-tiles per CTA)

    prep_vec<<<448, 256>>>(z, ml_wa, ml_ba, ml_wb, ml_bb, wz, bz);        // 1
    prep_xq<<<S_TOT / 8, 256>>>(x, m);                                    // 2
    prep_w1q<<<HID / 8, 256>>>(w1, wma);                                  // 3
    L1<<<GRB, 512, SM_L1>>>(xq1, xq2, xs, w1q1, w1q2, w1s, b1,
                            aq1, aq2, as, nullptr, HID);                  // 4 <-- ncu
    prep_wmq<<<5 * HID / 8, 256>>>(ml_w);
    prep_wcq<<<COL / 8, 256>>>(wc);
    reset_amax<<<7, 256>>>();

    // --- MLP ---
    LH<<<GRB, 512, SM_LH>>>(aq1, aq2, as, wmq1 + 0 * 65536, wmq2 + 0 * 65536, wms + 0,
                            be + 0,    bq1, bq2, bsc, nullptr, HID);
    LH<<<GRB, 512, SM_LH>>>(bq1, bq2, bsc, wmq1 + 1 * 65536, wmq2 + 1 * 65536, wms + 256,
                            be + 256,  aq1, aq2, as, nullptr, HID);
    LH<<<GRB, 512, SM_LH>>>(aq1, aq2, as, wmq1 + 2 * 65536, wmq2 + 2 * 65536, wms + 512,
                            be + 512,  bq1, bq2, bsc, nullptr, HID);
    sigma_q<<<S_TOT / 8, 256>>>(bq1, bq2, bsc, wsig, bsig, sig);
    LH<<<GRB, 512, SM_LH>>>(bq1, bq2, bsc, wmq1 + 3 * 65536, wmq2 + 3 * 65536, wms + 768,
                            be + 768,  aq1, aq2, as, nullptr, HID);
    LH<<<GRB, 512, SM_LH>>>(aq1, aq2, as, wmq1 + 4 * 65536, wmq2 + 4 * 65536, wms + 1024,
                            be + 1024, bq1, bq2, bsc, nullptr, HID);

    // --- fused wc head + compositing (feat + camax[0]) ---
    lwcomp<<<S_TOT / 128, 256, SM_LC>>>(bq1, bq2, bsc, wcq1, wcq2, wcs, bc,
                                        sig, dists, fth, ftl, camax + 0 * HID);

    // --- CNN weight transposes ---
    prep_twf<<<(TWF + 255) / 256, 256>>>(c2a_w, wt3f + 0 * TWF);
    prep_twf<<<(TWF + 255) / 256, 256>>>(c2b_w, wt3f + 1 * TWF);
    prep_twf<<<(TWF + 255) / 256, 256>>>(c3a_w, wt3f + 2 * TWF);
    prep_twf<<<(TWF + 255) / 256, 256>>>(c3b_w, wt3f + 3 * TWF);

    // --- CNN (int8 IMMA, runtime scale folding; fused quant+wreq) ---
    dim3 gC(2 * HH, 2);
    const int NQ  = (HWPIX * HID + 255) / 256;
    const int NQF = (HWPIX * COL + 255) / 256;

    qa_wr<COL, 1, COL><<<NQF + 32, 256>>>(fth, ftl, camax + 0 * HID, cq1, cq2,
                                          c1_w, cwq1, cwq2, cts, NQF);
    CV1<<<gC, 256, SMCV>>>(cq1, cq2, cwq1, cwq2, cts, c1_b, nullptr, nullptr,
                           nullptr, 0, yah, yal, camax + 1 * HID);

    qa_wr<HID, 9, HID><<<NQ + 32, 256>>>(yah, yal, camax + 1 * HID, cq1, cq2,
                                         wt3f + 0 * TWF, cwq1, cwq2, cts, NQ);
    CVA<<<gC, 256, SMCV>>>(cq1, cq2, cwq1, cwq2, cts, c2a_b, nullptr, nullptr,
                           nullptr, 0, ybh, ybl, camax + 2 * HID);

    qa_wr<HID, 9, HID><<<NQ + 32, 256>>>(ybh, ybl, camax + 2 * HID, cq1, cq2,
                                         wt3f + 1 * TWF, cwq1, cwq2, cts, NQ);
    CVB<<<gC, 256, SMCV>>>(cq1, cq2, cwq1, cwq2, cts, nullptr, yah, yal,
                           zcv, 0, ych, ycl, camax + 3 * HID);

    qa_wr<HID, 9, HID><<<NQ + 32, 256>>>(ych, ycl, camax + 3 * HID, cq1, cq2,
                                         wt3f + 2 * TWF, cwq1, cwq2, cts, NQ);
    CVA<<<gC, 256, SMCV>>>(cq1, cq2, cwq1, cwq2, cts, c3a_b, nullptr, nullptr,
                           nullptr, 0, ybh, ybl, camax + 4 * HID);

    qa_wr<HID, 9, HID><<<NQ + 32, 256>>>(ybh, ybl, camax + 4 * HID, cq1, cq2,
                                         wt3f + 3 * TWF, cwq1, cwq2, cts, NQ);
    CVB<<<gC, 256, SMCV>>>(cq1, cq2, cwq1, cwq2, cts, nullptr, ych, ycl,
                           zcv, 512, yah, yal, camax + 5 * HID);

    qa_wr<HID, 1, HID><<<NQ + 32, 256>>>(yah, yal, camax + 5 * HID, cq1, cq2,
                                         c4a_w, cwq1, cwq2, cts, NQ);
    CV4A<<<gC, 256, SMCV>>>(cq1, cq2, cwq1, cwq2, cts, c4a_b, nullptr, nullptr,
                            nullptr, 0, ybh, ybl, camax + 6 * HID);

    qa_wr<HID, 1, HID><<<NQ + 32, 256>>>(ybh, ybl, camax + 6 * HID, cq1, cq2,
                                         c4b_w, cwq1, cwq2, cts, NQ);
    CV4B<<<gC, 256, SMCV>>>(cq1, cq2, cwq1, cwq2, cts, c4b_b, yah, yal,
                            nullptr, 0, ych, ycl, nullptr);

    final_conv<<<HWPIX / 8, 256>>>(ych, ycl, c4_w, c4_b, out);

    (void)in_sizes; (void)n_in; (void)out_size;
}

// round 17
// speedup vs baseline: 1.0762x; 1.0137x over previous
#include <cuda_runtime.h>
#include <cuda_bf16.h>
#include <cstdint>

// ---------------------------------------------------------------------------
// Problem constants
// ---------------------------------------------------------------------------
#define HH      128
#define WW      128
#define MM      16
#define CIN     128
#define NC      7
#define HID     256
#define STY     256
#define COL     64
#define HWPIX   (HH * WW)            // 16384
#define S_TOT   (HWPIX * MM)         // 262144
#define KQ1     192                  // padded K for layer 1

#define QMAX    16256.0f             // 127 * 128
#define QDEN    (16256.0f * 16256.0f)

// ---------------------------------------------------------------------------
// Scratch (device globals)
// ---------------------------------------------------------------------------
__device__ int8_t d_xq1[(size_t)S_TOT * KQ1];
__device__ int8_t d_xq2[(size_t)S_TOT * KQ1];
__device__ float  d_xs[S_TOT];
__device__ int8_t d_aq1[(size_t)S_TOT * HID];
__device__ int8_t d_aq2[(size_t)S_TOT * HID];
__device__ float  d_as[S_TOT];
__device__ int8_t d_bq1[(size_t)S_TOT * HID];
__device__ int8_t d_bq2[(size_t)S_TOT * HID];
__device__ float  d_bsc[S_TOT];
__device__ int8_t d_w1q1[HID * KQ1];
__device__ int8_t d_w1q2[HID * KQ1];
__device__ float  d_w1s[HID];
__device__ int8_t d_wmq1[5 * HID * HID];
__device__ int8_t d_wmq2[5 * HID * HID];
__device__ float  d_wms[5 * HID];
__device__ int8_t d_wcq1[COL * HID];
__device__ int8_t d_wcq2[COL * HID];
__device__ float  d_wcs[COL];
// CNN: fp transposed 3x3 weights, runtime-requantized int8 weights, scales
__device__ float  d_wt3f[4 * 9 * HID * HID];     // [conv][tap][O][K] fp32
__device__ int8_t d_cwq1[9 * HID * HID];
__device__ int8_t d_cwq2[9 * HID * HID];
__device__ float  d_cts[HID];
__device__ float  d_camax[7 * HID];
// CNN activations: bf16 hi/lo pairs + int8 quantized planes
__device__ __nv_bfloat16 d_yah[HWPIX * HID];
__device__ __nv_bfloat16 d_yal[HWPIX * HID];
__device__ __nv_bfloat16 d_ybh[HWPIX * HID];
__device__ __nv_bfloat16 d_ybl[HWPIX * HID];
__device__ __nv_bfloat16 d_ych[HWPIX * HID];
__device__ __nv_bfloat16 d_ycl[HWPIX * HID];
__device__ __nv_bfloat16 d_feath[HWPIX * COL];
__device__ __nv_bfloat16 d_featl[HWPIX * COL];
__device__ int8_t d_cq1[HWPIX * HID];
__device__ int8_t d_cq2[HWPIX * HID];
__device__ float d_sig[S_TOT];
__device__ float d_alpha[5 * HID];
__device__ float d_beta[5 * HID];
__device__ float d_zc[4 * HID];

static __device__ __forceinline__ float lrelu(float v) {
    return v > 0.f ? v : 0.2f * v;
}

static __device__ __forceinline__ uint32_t smem_u32(const void* p) {
    uint32_t a;
    asm("{ .reg .u64 t; cvta.to.shared.u64 t, %1; cvt.u32.u64 %0, t; }" : "=r"(a) : "l"(p));
    return a;
}

static __device__ __forceinline__ void cpa16z(uint32_t dst, const void* src, uint32_t sz) {
    asm volatile("cp.async.cg.shared.global [%0], [%1], 16, %2;"
                 :: "r"(dst), "l"(src), "r"(sz));
}

static __device__ __forceinline__ void ldm_x4(uint32_t* r, uint32_t addr) {
    asm volatile("ldmatrix.sync.aligned.m8n8.x4.shared.b16 {%0,%1,%2,%3}, [%4];"
                 : "=r"(r[0]), "=r"(r[1]), "=r"(r[2]), "=r"(r[3]) : "r"(addr));
}

static __device__ __forceinline__ void imma16832(int* d, const uint32_t* a, const uint32_t* b) {
    asm volatile(
        "mma.sync.aligned.m16n8k32.row.col.s32.s8.s8.s32 "
        "{%0,%1,%2,%3}, {%4,%5,%6,%7}, {%8,%9}, {%0,%1,%2,%3};"
        : "+r"(d[0]), "+r"(d[1]), "+r"(d[2]), "+r"(d[3])
        : "r"(a[0]), "r"(a[1]), "r"(a[2]), "r"(a[3]), "r"(b[0]), "r"(b[1]));
}

static __device__ __forceinline__ uint32_t ldm_a_addr(uint32_t base, int lane) {
    return base + (uint32_t)(lane & 15) * 80 + (uint32_t)((lane >> 4) << 4);
}
static __device__ __forceinline__ uint32_t ldm_b_addr(uint32_t base, int lane) {
    const int n = (lane & 7) + ((lane >= 16) ? 8 : 0);
    const int k16 = ((lane >> 3) & 1) << 4;
    return base + (uint32_t)n * 80 + (uint32_t)k16;
}

static __device__ __forceinline__ void quant2(float v, float inv, int& q1, int& q2) {
    float qf = rintf(v * inv);
    int   q  = (int)qf;
    q1 = (int)rintf(qf * (1.f / 128.f));
    q2 = q - (q1 << 7);
}

static __device__ __forceinline__ void amax_atomic(float* addr, float v) {
    atomicMax(reinterpret_cast<int*>(addr), __float_as_int(v));
}

// ---------------------------------------------------------------------------
// Prep kernels
// ---------------------------------------------------------------------------
__global__ void prep_vec(const float* __restrict__ z,
                         const float* __restrict__ wa, const float* __restrict__ ba,
                         const float* __restrict__ wb, const float* __restrict__ bb,
                         const float* __restrict__ wz, const float* __restrict__ bz) {
    int warp = (blockIdx.x * blockDim.x + threadIdx.x) >> 5;
    int lane = threadIdx.x & 31;
    if (warp >= 3584) return;
    const float* row; float bias; float* out;
    if (warp < 1280)      { row = wa + (size_t)warp * STY; bias = ba[warp]; out = d_alpha + warp; }
    else if (warp < 2560) { int i = warp - 1280; row = wb + (size_t)i * STY; bias = bb[i]; out = d_beta + i; }
    else                  { int i = warp - 2560; row = wz + (size_t)i * STY; bias = bz[i]; out = d_zc + i; }
    float acc = 0.f;
    #pragma unroll
    for (int t = 0; t < 8; t++) acc += z[lane + 32 * t] * row[lane + 32 * t];
    #pragma unroll
    for (int off = 16; off; off >>= 1) acc += __shfl_xor_sync(0xFFFFFFFFu, acc, off);
    if (lane == 0) *out = acc + bias;
}

static __device__ __forceinline__ float warp_amax(float a) {
    #pragma unroll
    for (int off = 16; off; off >>= 1) a = fmaxf(a, __shfl_xor_sync(0xFFFFFFFFu, a, off));
    return a;
}

__global__ void prep_xq(const float* __restrict__ x, const float* __restrict__ m) {
    int s = blockIdx.x * 8 + (threadIdx.x >> 5);
    int lane = threadIdx.x & 31;
    if (s >= S_TOT) return;
    float v[6];
    #pragma unroll
    for (int t = 0; t < 6; t++) {
        int c = lane + 32 * t;
        float val = 0.f;
        if (c < CIN)           val = x[(size_t)s * CIN + c];
        else if (c < CIN + NC) val = m[(size_t)s * NC + (c - CIN)];
        v[t] = val;
    }
    float am = 0.f;
    #pragma unroll
    for (int t = 0; t < 6; t++) am = fmaxf(am, fabsf(v[t]));
    am = warp_amax(am);
    if (lane == 0) d_xs[s] = am;
    float inv = QMAX / fmaxf(am, 1e-20f);
    #pragma unroll
    for (int t = 0; t < 6; t++) {
        int c = lane + 32 * t;
        int q1, q2; quant2(v[t], inv, q1, q2);
        d_xq1[(size_t)s * KQ1 + c] = (int8_t)q1;
        d_xq2[(size_t)s * KQ1 + c] = (int8_t)q2;
    }
}

__global__ void prep_w1q(const float* __restrict__ w1, const float* __restrict__ wma) {
    int o = blockIdx.x * 8 + (threadIdx.x >> 5);
    int lane = threadIdx.x & 31;
    if (o >= HID) return;
    float v[6];
    #pragma unroll
    for (int t = 0; t < 6; t++) {
        int c = lane + 32 * t;
        float val = 0.f;
        if (c < CIN)           val = w1[(size_t)o * CIN + c];
        else if (c < CIN + NC) val = wma[(size_t)o * NC + (c - CIN)];
        v[t] = val;
    }
    float am = 0.f;
    #pragma unroll
    for (int t = 0; t < 6; t++) am = fmaxf(am, fabsf(v[t]));
    am = warp_amax(am);
    if (lane == 0) d_w1s[o] = am;
    float inv = QMAX / fmaxf(am, 1e-20f);
    #pragma unroll
    for (int t = 0; t < 6; t++) {
        int c = lane + 32 * t;
        int q1, q2; quant2(v[t], inv, q1, q2);
        d_w1q1[(size_t)o * KQ1 + c] = (int8_t)q1;
        d_w1q2[(size_t)o * KQ1 + c] = (int8_t)q2;
    }
}

__global__ void prep_wmq(const float* __restrict__ mlw) {
    int r = blockIdx.x * 8 + (threadIdx.x >> 5);
    int lane = threadIdx.x & 31;
    if (r >= 5 * HID) return;
    int layer = r >> 8;
    float v[8];
    #pragma unroll
    for (int t = 0; t < 8; t++) {
        int k = lane + 32 * t;
        v[t] = mlw[(size_t)r * HID + k] * d_alpha[layer * HID + k];
    }
    float am = 0.f;
    #pragma unroll
    for (int t = 0; t < 8; t++) am = fmaxf(am, fabsf(v[t]));
    am = warp_amax(am);
    if (lane == 0) d_wms[r] = am;
    float inv = QMAX / fmaxf(am, 1e-20f);
    #pragma unroll
    for (int t = 0; t < 8; t++) {
        int k = lane + 32 * t;
        int q1, q2; quant2(v[t], inv, q1, q2);
        d_wmq1[(size_t)r * HID + k] = (int8_t)q1;
        d_wmq2[(size_t)r * HID + k] = (int8_t)q2;
    }
}

__global__ void prep_wcq(const float* __restrict__ wc) {
    int o = blockIdx.x * 8 + (threadIdx.x >> 5);
    int lane = threadIdx.x & 31;
    if (o >= COL) return;
    float v[8];
    #pragma unroll
    for (int t = 0; t < 8; t++) v[t] = wc[(size_t)o * HID + lane + 32 * t];
    float am = 0.f;
    #pragma unroll
    for (int t = 0; t < 8; t++) am = fmaxf(am, fabsf(v[t]));
    am = warp_amax(am);
    if (lane == 0) d_wcs[o] = am;
    float inv = QMAX / fmaxf(am, 1e-20f);
    #pragma unroll
    for (int t = 0; t < 8; t++) {
        int q1, q2; quant2(v[t], inv, q1, q2);
        d_wcq1[(size_t)o * HID + lane + 32 * t] = (int8_t)q1;
        d_wcq2[(size_t)o * HID + lane + 32 * t] = (int8_t)q2;
    }
}

__global__ void prep_twf(const float* __restrict__ w, float* __restrict__ out) {
    int idx = blockIdx.x * blockDim.x + threadIdx.x;
    if (idx >= 9 * HID * HID) return;
    int tap = idx / (HID * HID);
    int ok  = idx - tap * (HID * HID);
    out[idx] = w[(size_t)ok * 9 + tap];
}

__global__ void reset_amax() {
    int idx = blockIdx.x * blockDim.x + threadIdx.x;
    if (idx < 7 * HID) d_camax[idx] = 0.f;
}

// ---------------------------------------------------------------------------
// Fused activation-quant + weight-requant.
// ---------------------------------------------------------------------------
template<int C, int TAPS, int K>
__global__ void qa_wr(const __nv_bfloat16* __restrict__ hi,
                      const __nv_bfloat16* __restrict__ lo,
                      const float* __restrict__ camax,
                      int8_t* __restrict__ q1p, int8_t* __restrict__ q2p,
                      const float* __restrict__ wsrc,
                      int8_t* __restrict__ wq1, int8_t* __restrict__ wq2,
                      float* __restrict__ Ts, int nq) {
    if ((int)blockIdx.x < nq) {
        int idx = blockIdx.x * 256 + threadIdx.x;
        if (idx >= HWPIX * C) return;
        int c = idx & (C - 1);
        float v = __bfloat162float(hi[idx]) + __bfloat162float(lo[idx]);
        float inv = QMAX / fmaxf(camax[c], 1e-20f);
        int q1, q2; quant2(v, inv, q1, q2);
        q1p[idx] = (int8_t)q1;
        q2p[idx] = (int8_t)q2;
    } else {
        int o = (blockIdx.x - nq) * 8 + (threadIdx.x >> 5);
        int lane = threadIdx.x & 31;
        if (o >= HID) return;
        const int E = TAPS * K;
        float am = 0.f;
        for (int e = lane; e < E; e += 32) {
            int tap = e / K, k = e - tap * K;
            float u = wsrc[(size_t)tap * (HID * K) + (size_t)o * K + k] * camax[k];
            am = fmaxf(am, fabsf(u));
        }
        am = warp_amax(am);
        if (lane == 0) Ts[o] = am / QDEN;
        float inv = QMAX / fmaxf(am, 1e-20f);
        for (int e = lane; e < E; e += 32) {
            int tap = e / K, k = e - tap * K;
            size_t idx = (size_t)tap * (HID * K) + (size_t)o * K + k;
            float u = wsrc[idx] * camax[k];
            int q1, q2; quant2(u, inv, q1, q2);
            wq1[idx] = (int8_t)q1;
            wq2[idx] = (int8_t)q2;
        }
    }
}

// ---------------------------------------------------------------------------
// MLP int8 GEMM, B-resident; 2 K-chunks per barrier, 3 rotating A buffers.
// DO_SIG: fuse sigma row-dot (wsig) into the epilogue via fixed-slot smem
// reduction (8 slots/row, single writer each -> deterministic).
// ---------------------------------------------------------------------------
template<int NTHR, int MT, int MTILES, int NT, int K, bool LRELU_, bool QOUT, bool DO_SIG>
__global__ void __launch_bounds__(NTHR)
imma_brg(const int8_t* __restrict__ Aq1, const int8_t* __restrict__ Aq2,
         const float* __restrict__ As,
         const int8_t* __restrict__ Bq1, const int8_t* __restrict__ Bq2,
         const float* __restrict__ Bs,
         const float* __restrict__ bias,
         int8_t* __restrict__ Oq1, int8_t* __restrict__ Oq2, float* __restrict__ Os,
         float* __restrict__ Of, int OC,
         const float* __restrict__ wsig, const float* __restrict__ bsig,
         float* __restrict__ sigout) {
    extern __shared__ char smem[];
    constexpr int NCH  = K / 64;
    constexpr int NHALF = (NCH + 1) / 2;
    constexpr int NGI2 = MTILES * NHALF;
    constexpr int BSL  = NT * 80;
    constexpr int ASL  = MT * 80;
    constexpr int CSL  = 2 * ASL;            // one chunk, both planes
    constexpr int ABUF = 2 * CSL;            // one buffer holds 2 chunks
    constexpr int B2OFF = NCH * BSL;
    constexpr int AO   = 2 * NCH * BSL;
    constexpr int SFO  = AO + 3 * ABUF;
    constexpr int SGO  = SFO + MT * 4;       // sigma slot buffer (MT*8 floats)
    constexpr int NW   = NTHR / 32;
    constexpr int WN   = NT / 32;
    constexpr int WM   = NW / WN;
    constexpr int MI   = MT / (16 * WM);

    const uint32_t sb = smem_u32(smem);
    const int tid = threadIdx.x;
    const int lane = tid & 31, wid = tid >> 5;
    const int wn = wid % WN, wm = wid / WN;
    const int g = lane >> 2, q = lane & 3;
    const int rbase0 = blockIdx.x * (MT * MTILES);

    // ---- B: all chunks, both planes, once ----
    for (int idx = tid; idx < NCH * NT * 4; idx += NTHR) {
        const int ch = idx / (NT * 4);
        const int rem = idx - ch * (NT * 4);
        const int row = rem >> 2, cc = rem & 3;
        const size_t go = (size_t)row * K + ch * 64 + cc * 16;
        const uint32_t d = sb + ch * BSL + row * 80 + cc * 16;
        cpa16z(d,         Bq1 + go, 16);
        cpa16z(d + B2OFF, Bq2 + go, 16);
    }
    auto load_A2 = [&](int bufi, int gi2) {
        const int mt = gi2 / NHALF, h = gi2 - mt * NHALF;
        const int ncc = (2 * h + 2 <= NCH) ? 2 : 1;
        for (int idx = tid; idx < ncc * MT * 4; idx += NTHR) {
            const int ci = idx / (MT * 4);
            const int rem = idx - ci * (MT * 4);
            const int row = rem >> 2, cc4 = rem & 3;
            const int c = 2 * h + ci;
            const size_t go = (size_t)(rbase0 + mt * MT + row) * K + c * 64 + cc4 * 16;
            const uint32_t d = sb + AO + bufi * ABUF + ci * CSL + row * 80 + cc4 * 16;
            cpa16z(d,       Aq1 + go, 16);
            cpa16z(d + ASL, Aq2 + go, 16);
        }
    };
    load_A2(0, 0);
    asm volatile("cp.async.commit_group;" ::: "memory");

    int acc1[MI][4][4], acc2[MI][4][4];
    #pragma unroll
    for (int i = 0; i < MI; i++)
        #pragma unroll
        for (int j = 0; j < 4; j++)
            #pragma unroll
            for (int r = 0; r < 4; r++) { acc1[i][j][r] = 0; acc2[i][j][r] = 0; }

    float* sf  = reinterpret_cast<float*>(smem + SFO);
    float* sgb = reinterpret_cast<float*>(smem + SGO);
    int buf = 0, nbuf = 1;

    for (int gi2 = 0; gi2 < NGI2; gi2++) {
        if (gi2 + 1 < NGI2) {
            load_A2(nbuf, gi2 + 1);
            asm volatile("cp.async.commit_group;" ::: "memory");
            asm volatile("cp.async.wait_group 1;" ::: "memory");
        } else {
            asm volatile("cp.async.wait_group 0;" ::: "memory");
        }
        __syncthreads();
        const int mt = gi2 / NHALF, h = gi2 - mt * NHALF;
        const int ncc = (2 * h + 2 <= NCH) ? 2 : 1;
        for (int ci = 0; ci < ncc; ci++) {
            const int c = 2 * h + ci;
            const uint32_t Ab = sb + AO + buf * ABUF + ci * CSL;
            const uint32_t Bb = sb + c * BSL;
            #pragma unroll
            for (int kk = 0; kk < 2; kk++) {
                const int koff = kk * 32;
                uint32_t a1[MI][4], a2[MI][4];
                #pragma unroll
                for (int i = 0; i < MI; i++) {
                    const uint32_t r0 = ldm_a_addr(Ab + (uint32_t)(wm * MI * 16 + i * 16) * 80 + koff, lane);
                    ldm_x4(a1[i], r0);
                    ldm_x4(a2[i], r0 + ASL);
                }
                uint32_t b1[4][2], b2[4][2];
                #pragma unroll
                for (int jp = 0; jp < 2; jp++) {
                    const uint32_t r0 = ldm_b_addr(Bb + (uint32_t)(wn * 32 + jp * 16) * 80 + koff, lane);
                    uint32_t t[4];
                    ldm_x4(t, r0);
                    b1[2 * jp][0] = t[0]; b1[2 * jp][1] = t[1];
                    b1[2 * jp + 1][0] = t[2]; b1[2 * jp + 1][1] = t[3];
                    ldm_x4(t, r0 + B2OFF);
                    b2[2 * jp][0] = t[0]; b2[2 * jp][1] = t[1];
                    b2[2 * jp + 1][0] = t[2]; b2[2 * jp + 1][1] = t[3];
                }
                #pragma unroll
                for (int i = 0; i < MI; i++)
                    #pragma unroll
                    for (int j = 0; j < 4; j++) {
                        imma16832(acc1[i][j], a1[i], b1[j]);
                        imma16832(acc2[i][j], a1[i], b2[j]);
                        imma16832(acc2[i][j], a2[i], b1[j]);
                    }
            }
        }
        buf = nbuf; nbuf = (nbuf == 2) ? 0 : nbuf + 1;

        if (h == NHALF - 1) {
            // ---- epilogue for m-tile mt ----
            const int rbase = rbase0 + mt * MT;
            if (QOUT) {
                for (int i2 = tid; i2 < MT; i2 += NTHR) sf[i2] = 0.f;
                __syncthreads();
            }
            float sbv[4][2], bv[4][2], wsv[4][2];
            #pragma unroll
            for (int j = 0; j < 4; j++) {
                const int col0 = wn * 32 + j * 8 + q * 2;
                sbv[j][0] = Bs[col0];     sbv[j][1] = Bs[col0 + 1];
                bv[j][0]  = bias[col0];   bv[j][1]  = bias[col0 + 1];
                if (DO_SIG) { wsv[j][0] = wsig[col0]; wsv[j][1] = wsig[col0 + 1]; }
            }
            #pragma unroll
            for (int i = 0; i < MI; i++) {
                #pragma unroll
                for (int h2 = 0; h2 < 2; h2++) {
                    const int lrow = wm * MI * 16 + i * 16 + g + h2 * 8;
                    const float sa = As[rbase + lrow] * (1.f / QDEN);
                    float rmax = 0.f, rp = 0.f;
                    #pragma unroll
                    for (int j = 0; j < 4; j++) {
                        float t0 = 16384.f * (float)acc1[i][j][h2 * 2 + 0] + 128.f * (float)acc2[i][j][h2 * 2 + 0];
                        float t1 = 16384.f * (float)acc1[i][j][h2 * 2 + 1] + 128.f * (float)acc2[i][j][h2 * 2 + 1];
                        float v0 = sa * sbv[j][0] * t0 + bv[j][0];
                        float v1 = sa * sbv[j][1] * t1 + bv[j][1];
                        if (LRELU_) { v0 = lrelu(v0); v1 = lrelu(v1); }
                        acc1[i][j][h2 * 2 + 0] = __float_as_int(v0);
                        acc1[i][j][h2 * 2 + 1] = __float_as_int(v1);
                        rmax = fmaxf(rmax, fmaxf(fabsf(v0), fabsf(v1)));
                        if (DO_SIG) rp += v0 * wsv[j][0] + v1 * wsv[j][1];
                    }
                    if (QOUT) {
                        rmax = fmaxf(rmax, __shfl_xor_sync(0xFFFFFFFFu, rmax, 1));
                        rmax = fmaxf(rmax, __shfl_xor_sync(0xFFFFFFFFu, rmax, 2));
                        if (q == 0) amax_atomic(&sf[lrow], rmax);
                    }
                    if (DO_SIG) {
                        rp += __shfl_xor_sync(0xFFFFFFFFu, rp, 1);
                        rp += __shfl_xor_sync(0xFFFFFFFFu, rp, 2);
                        if (q == 0) sgb[lrow * 8 + wn] = rp;
                    }
                }
            }
            if (QOUT) {
                __syncthreads();
                if (DO_SIG && tid < MT) {
                    float s = 0.f;
                    #pragma unroll
                    for (int k2 = 0; k2 < 8; k2++) s += sgb[tid * 8 + k2];
                    sigout[rbase + tid] = s + bsig[0];
                }
                #pragma unroll
                for (int i = 0; i < MI; i++) {
                    #pragma unroll
                    for (int h2 = 0; h2 < 2; h2++) {
                        const int lrow = wm * MI * 16 + i * 16 + g + h2 * 8;
                        const int grow = rbase + lrow;
                        const float mx = sf[lrow];
                        const float inv = QMAX / fmaxf(mx, 1e-20f);
                        if (wn == 0 && q == 0) Os[grow] = mx;
                        #pragma unroll
                        for (int j = 0; j < 4; j++) {
                            const int col0 = wn * 32 + j * 8 + q * 2;
                            float v0 = __int_as_float(acc1[i][j][h2 * 2 + 0]);
                            float v1 = __int_as_float(acc1[i][j][h2 * 2 + 1]);
                            int p1, p2, r1, r2;
                            quant2(v0, inv, p1, p2);
                            quant2(v1, inv, r1, r2);
                            char2 o1; o1.x = (char)p1; o1.y = (char)r1;
                            char2 o2; o2.x = (char)p2; o2.y = (char)r2;
                            *reinterpret_cast<char2*>(Oq1 + (size_t)grow * OC + col0) = o1;
                            *reinterpret_cast<char2*>(Oq2 + (size_t)grow * OC + col0) = o2;
                        }
                    }
                }
                __syncthreads();
            } else {
                #pragma unroll
                for (int i = 0; i < MI; i++) {
                    #pragma unroll
                    for (int h2 = 0; h2 < 2; h2++) {
                        const int lrow = wm * MI * 16 + i * 16 + g + h2 * 8;
                        const int grow = rbase + lrow;
                        #pragma unroll
                        for (int j = 0; j < 4; j++) {
                            const int col0 = wn * 32 + j * 8 + q * 2;
                            float2 v;
                            v.x = __int_as_float(acc1[i][j][h2 * 2 + 0]);
                            v.y = __int_as_float(acc1[i][j][h2 * 2 + 1]);
                            *reinterpret_cast<float2*>(Of + (size_t)grow * OC + col0) = v;
                        }
                    }
                }
            }
            #pragma unroll
            for (int i = 0; i < MI; i++)
                #pragma unroll
                for (int j = 0; j < 4; j++)
                    #pragma unroll
                    for (int r = 0; r < 4; r++) { acc1[i][j][r] = 0; acc2[i][j][r] = 0; }
        }
    }
}

// ---------------------------------------------------------------------------
// Fused wc head + compositing
// ---------------------------------------------------------------------------
__global__ void __launch_bounds__(256)
lwcomp(const int8_t* __restrict__ Aq1, const int8_t* __restrict__ Aq2,
       const float* __restrict__ As,
       const int8_t* __restrict__ Bq1, const int8_t* __restrict__ Bq2,
       const float* __restrict__ Bs, const float* __restrict__ bias,
       const float* __restrict__ sigma, const float* __restrict__ dists,
       __nv_bfloat16* __restrict__ feath, __nv_bfloat16* __restrict__ featl,
       float* __restrict__ amax_out) {
    extern __shared__ char smem[];
    constexpr int MT = 128, NT = 64, K = HID;
    constexpr int NCH   = K / 64;
    constexpr int ASLAB = MT * 80;
    constexpr int BSLAB = NT * 80;
    constexpr int BOFF  = 2 * ASLAB;
    constexpr int BUF   = 2 * ASLAB + 2 * BSLAB;
    constexpr int WN = 2, WM = 4, MI = 2;
    constexpr int TSTR = 68;

    const uint32_t sb = smem_u32(smem);
    const int tid = threadIdx.x;
    const int lane = tid & 31, wid = tid >> 5;
    const int wn = wid % WN, wm = wid / WN;
    const int g = lane >> 2, q = lane & 3;
    const int rbase = blockIdx.x * MT;
    const int pb = blockIdx.x * 8;

    auto load_chunk = [&](int bufi, int c) {
        const uint32_t base = sb + bufi * BUF;
        const int k0 = c * 64;
        for (int idx = tid; idx < MT * 4; idx += 256) {
            const int row = idx >> 2, cc = idx & 3;
            const size_t go = (size_t)(rbase + row) * K + k0 + cc * 16;
            const uint32_t d = base + row * 80 + cc * 16;
            cpa16z(d,         Aq1 + go, 16);
            cpa16z(d + ASLAB, Aq2 + go, 16);
        }
        for (int idx = tid; idx < NT * 4; idx += 256) {
            const int row = idx >> 2, cc = idx & 3;
            const size_t go = (size_t)row * K + k0 + cc * 16;
            const uint32_t d = base + BOFF + row * 80 + cc * 16;
            cpa16z(d,         Bq1 + go, 16);
            cpa16z(d + BSLAB, Bq2 + go, 16);
        }
        asm volatile("cp.async.commit_group;" ::: "memory");
    };

    int acc1[MI][4][4], acc2[MI][4][4];
    #pragma unroll
    for (int i = 0; i < MI; i++)
        #pragma unroll
        for (int j = 0; j < 4; j++)
            #pragma unroll
            for (int r = 0; r < 4; r++) { acc1[i][j][r] = 0; acc2[i][j][r] = 0; }

    load_chunk(0, 0);
    int buf = 0, nbuf = 1;
    for (int c = 0; c < NCH; c++) {
        if (c + 1 < NCH) {
            load_chunk(nbuf, c + 1);
            asm volatile("cp.async.wait_group 1;" ::: "memory");
        } else {
            asm volatile("cp.async.wait_group 0;" ::: "memory");
        }
        __syncthreads();
        const uint32_t Ab = sb + buf * BUF;
        const uint32_t Bb = Ab + BOFF;
        #pragma unroll
        for (int kk = 0; kk < 2; kk++) {
            const int koff = kk * 32;
            uint32_t a1[MI][4], a2[MI][4];
            #pragma unroll
            for (int i = 0; i < MI; i++) {
                const uint32_t r0 = ldm_a_addr(Ab + (uint32_t)(wm * MI * 16 + i * 16) * 80 + koff, lane);
                ldm_x4(a1[i], r0);
                ldm_x4(a2[i], r0 + ASLAB);
            }
            uint32_t b1[4][2], b2[4][2];
            #pragma unroll
            for (int jp = 0; jp < 2; jp++) {
                const uint32_t r0 = ldm_b_addr(Bb + (uint32_t)(wn * 32 + jp * 16) * 80 + koff, lane);
                uint32_t t[4];
                ldm_x4(t, r0);
                b1[2 * jp][0] = t[0]; b1[2 * jp][1] = t[1];
                b1[2 * jp + 1][0] = t[2]; b1[2 * jp + 1][1] = t[3];
                ldm_x4(t, r0 + BSLAB);
                b2[2 * jp][0] = t[0]; b2[2 * jp][1] = t[1];
                b2[2 * jp + 1][0] = t[2]; b2[2 * jp + 1][1] = t[3];
            }
            #pragma unroll
            for (int i = 0; i < MI; i++)
                #pragma unroll
                for (int j = 0; j < 4; j++) {
                    imma16832(acc1[i][j], a1[i], b1[j]);
                    imma16832(acc2[i][j], a1[i], b2[j]);
                    imma16832(acc2[i][j], a2[i], b1[j]);
                }
        }
        buf = nbuf; nbuf = (nbuf == 2) ? 0 : nbuf + 1;
    }
    __syncthreads();

    float* tile = reinterpret_cast<float*>(smem);
    float* wg   = reinterpret_cast<float*>(smem) + MT * TSTR;
    float* sch  = wg + 8 * MM;
    #pragma unroll
    for (int j = 0; j < 4; j++) {
        const int col0 = wn * 32 + j * 8 + q * 2;
        const float sb0 = Bs[col0], sb1 = Bs[col0 + 1];
        const float b0 = bias[col0], b1 = bias[col0 + 1];
        #pragma unroll
        for (int i = 0; i < MI; i++) {
            #pragma unroll
            for (int h = 0; h < 2; h++) {
                const int lrow = wm * MI * 16 + i * 16 + g + h * 8;
                const float sa = As[rbase + lrow] * (1.f / QDEN);
                float t0 = 16384.f * (float)acc1[i][j][h * 2 + 0] + 128.f * (float)acc2[i][j][h * 2 + 0];
                float t1 = 16384.f * (float)acc1[i][j][h * 2 + 1] + 128.f * (float)acc2[i][j][h * 2 + 1];
                float2 v;
                v.x = sa * sb0 * t0 + b0;
                v.y = sa * sb1 * t1 + b1;
                *reinterpret_cast<float2*>(&tile[lrow * TSTR + col0]) = v;
            }
        }
    }
    if (tid < 8) {
        const int pix = pb + tid;
        float T = 1.f;
        #pragma unroll
        for (int m2 = 0; m2 < MM; m2++) {
            float sg = sigma[pix * MM + m2];
            sg = sg > 0.f ? sg : 0.f;
            float a = 1.f - expf(-sg * dists[pix * MM + m2]);
            wg[tid * MM + m2] = a * T;
            T *= (1.f - a + 1e-10f);
        }
    }
    if (tid >= 64 && tid < 128) sch[tid - 64] = 0.f;
    __syncthreads();

    const int c0 = tid & 63;
    float lm = 0.f;
    #pragma unroll
    for (int t2 = 0; t2 < 2; t2++) {
        const int o = tid + t2 * 256;
        const int pix = o >> 6;
        float acc = 0.f;
        #pragma unroll
        for (int m2 = 0; m2 < MM; m2++)
            acc += wg[pix * MM + m2] * tile[(pix * MM + m2) * TSTR + c0];
        __nv_bfloat16 hbf = __float2bfloat16(acc);
        feath[(size_t)(pb + pix) * COL + c0] = hbf;
        featl[(size_t)(pb + pix) * COL + c0] = __float2bfloat16(acc - __bfloat162float(hbf));
        lm = fmaxf(lm, fabsf(acc));
    }
    amax_atomic(&sch[c0], lm);
    __syncthreads();
    if (tid < 64) amax_atomic(&amax_out[tid], sch[tid]);
}

// ---------------------------------------------------------------------------
// CNN int8 conv: 256 threads, tile 64 px x 128 ch, triple-buffered.
// ---------------------------------------------------------------------------
template<int TAPS, int K, bool HAS_BIAS, bool HAS_RES, bool HAS_MOD, bool DO_AMAX>
__global__ void __launch_bounds__(256)
conv_q(const int8_t* __restrict__ Aq1, const int8_t* __restrict__ Aq2,
       const int8_t* __restrict__ Wq1, const int8_t* __restrict__ Wq2,
       const float* __restrict__ Ts, const float* __restrict__ bias,
       const __nv_bfloat16* __restrict__ ResH, const __nv_bfloat16* __restrict__ ResL,
       const float* __restrict__ zc, int modoff,
       __nv_bfloat16* __restrict__ Chi, __nv_bfloat16* __restrict__ Clo,
       float* __restrict__ amax_out) {
    extern __shared__ char smem[];
    constexpr int KCH    = K / 64;
    constexpr int NCHUNK = TAPS * KCH;
    constexpr int ASLAB  = 64 * 80;
    constexpr int BSLAB  = 128 * 80;
    constexpr int BOFF   = 2 * ASLAB;
    constexpr int BUF    = 2 * ASLAB + 2 * BSLAB;
    constexpr int MI     = 2;

    const uint32_t sb = smem_u32(smem);
    const int tid = threadIdx.x;
    const int lane = tid & 31, wid = tid >> 5;
    const int wn = wid & 3, wm = wid >> 2;
    const int g = lane >> 2, q = lane & 3;
    const int o0 = blockIdx.y * 128;
    const int py0 = (int)blockIdx.x >> 1;
    const int px0 = ((int)blockIdx.x & 1) << 6;

    auto load_chunk = [&](int bufi, int chunk) {
        const int tap = (TAPS == 9) ? (chunk / KCH) : 0;
        const int k0  = ((TAPS == 9) ? (chunk - tap * KCH) : chunk) * 64;
        const uint32_t base = sb + bufi * BUF;
        {
            const int row = tid >> 2, cc = tid & 3;
            uint32_t sz = 16;
            int pix;
            if (TAPS == 9) {
                const int dy = tap / 3 - 1, dx = tap % 3 - 1;
                const int py = py0 + dy, px = px0 + row + dx;
                const bool ok = (py >= 0) && (py < HH) && (px >= 0) && (px < WW);
                sz = ok ? 16u : 0u;
                pix = ok ? (py * WW + px) : 0;
            } else {
                pix = py0 * WW + px0 + row;
            }
            const size_t go = (size_t)pix * K + k0 + cc * 16;
            const uint32_t d = base + row * 80 + cc * 16;
            cpa16z(d,         Aq1 + go, sz);
            cpa16z(d + ASLAB, Aq2 + go, sz);
        }
        for (int idx = tid; idx < 128 * 4; idx += 256) {
            const int row = idx >> 2, cc = idx & 3;
            const size_t go = (size_t)tap * (HID * K) + (size_t)(o0 + row) * K + k0 + cc * 16;
            const uint32_t d = base + BOFF + row * 80 + cc * 16;
            cpa16z(d,         Wq1 + go, 16);
            cpa16z(d + BSLAB, Wq2 + go, 16);
        }
        asm volatile("cp.async.commit_group;" ::: "memory");
    };

    int acc1[MI][4][4], acc2[MI][4][4];
    #pragma unroll
    for (int i = 0; i < MI; i++)
        #pragma unroll
        for (int j = 0; j < 4; j++)
            #pragma unroll
            for (int r = 0; r < 4; r++) { acc1[i][j][r] = 0; acc2[i][j][r] = 0; }

    load_chunk(0, 0);
    int buf = 0, nbuf = 1;
    for (int c = 0; c < NCHUNK; c++) {
        if (c + 1 < NCHUNK) {
            load_chunk(nbuf, c + 1);
            asm volatile("cp.async.wait_group 1;" ::: "memory");
        } else {
            asm volatile("cp.async.wait_group 0;" ::: "memory");
        }
        __syncthreads();
        const uint32_t Ab = sb + buf * BUF;
        const uint32_t Bb = Ab + BOFF;
        #pragma unroll
        for (int kk = 0; kk < 2; kk++) {
            const int koff = kk * 32;
            uint32_t a1[MI][4], a2[MI][4];
            #pragma unroll
            for (int i = 0; i < MI; i++) {
                const uint32_t r0 = ldm_a_addr(Ab + (uint32_t)(wm * 32 + i * 16) * 80 + koff, lane);
                ldm_x4(a1[i], r0);
                ldm_x4(a2[i], r0 + ASLAB);
            }
            uint32_t b1[4][2], b2[4][2];
            #pragma unroll
            for (int jp = 0; jp < 2; jp++) {
                const uint32_t r0 = ldm_b_addr(Bb + (uint32_t)(wn * 32 + jp * 16) * 80 + koff, lane);
                uint32_t t[4];
                ldm_x4(t, r0);
                b1[2 * jp][0] = t[0]; b1[2 * jp][1] = t[1];
                b1[2 * jp + 1][0] = t[2]; b1[2 * jp + 1][1] = t[3];
                ldm_x4(t, r0 + BSLAB);
                b2[2 * jp][0] = t[0]; b2[2 * jp][1] = t[1];
                b2[2 * jp + 1][0] = t[2]; b2[2 * jp + 1][1] = t[3];
            }
            #pragma unroll
            for (int i = 0; i < MI; i++)
                #pragma unroll
                for (int j = 0; j < 4; j++) {
                    imma16832(acc1[i][j], a1[i], b1[j]);
                    imma16832(acc2[i][j], a1[i], b2[j]);
                    imma16832(acc2[i][j], a2[i], b1[j]);
                }
        }
        buf = nbuf; nbuf = (nbuf == 2) ? 0 : nbuf + 1;
    }

    __syncthreads();
    float* sch = reinterpret_cast<float*>(smem);
    if (DO_AMAX) {
        if (tid < 128) sch[tid] = 0.f;
        __syncthreads();
    }
    #pragma unroll
    for (int j = 0; j < 4; j++) {
        const int cl = wn * 32 + j * 8 + q * 2;
        const int colg = o0 + cl;
        const float t0 = Ts[colg], t1 = Ts[colg + 1];
        const float b0 = HAS_BIAS ? bias[colg]     : 0.f;
        const float b1 = HAS_BIAS ? bias[colg + 1] : 0.f;
        float sc0 = 1.f, sc1 = 1.f, sh0 = 0.f, sh1 = 0.f;
        if (HAS_MOD) {
            sc0 = zc[modoff + colg] + 1.f;       sc1 = zc[modoff + colg + 1] + 1.f;
            sh0 = zc[modoff + HID + colg];       sh1 = zc[modoff + HID + colg + 1];
        }
        float lm0 = 0.f, lm1 = 0.f;
        #pragma unroll
        for (int i = 0; i < MI; i++) {
            #pragma unroll
            for (int h = 0; h < 2; h++) {
                const int pix = py0 * WW + px0 + wm * 32 + i * 16 + g + h * 8;
                float v0 = t0 * (16384.f * (float)acc1[i][j][h * 2 + 0] + 128.f * (float)acc2[i][j][h * 2 + 0]) + b0;
                float v1 = t1 * (16384.f * (float)acc1[i][j][h * 2 + 1] + 128.f * (float)acc2[i][j][h * 2 + 1]) + b1;
                if (HAS_RES) {
                    __nv_bfloat162 rh = *reinterpret_cast<const __nv_bfloat162*>(ResH + (size_t)pix * HID + colg);
                    __nv_bfloat162 rl = *reinterpret_cast<const __nv_bfloat162*>(ResL + (size_t)pix * HID + colg);
                    v0 += __bfloat162float(rh.x) + __bfloat162float(rl.x);
                    v1 += __bfloat162float(rh.y) + __bfloat162float(rl.y);
                }
                if (HAS_MOD) { v0 = v0 * sc0 + sh0; v1 = v1 * sc1 + sh1; }
                v0 = lrelu(v0); v1 = lrelu(v1);
                if (DO_AMAX) { lm0 = fmaxf(lm0, fabsf(v0)); lm1 = fmaxf(lm1, fabsf(v1)); }
                __nv_bfloat162 hp = __floats2bfloat162_rn(v0, v1);
                float r0 = v0 - __bfloat162float(hp.x);
                float r1 = v1 - __bfloat162float(hp.y);
                __nv_bfloat162 lp = __floats2bfloat162_rn(r0, r1);
                *reinterpret_cast<__nv_bfloat162*>(Chi + (size_t)pix * HID + colg) = hp;
                *reinterpret_cast<__nv_bfloat162*>(Clo + (size_t)pix * HID + colg) = lp;
            }
        }
        if (DO_AMAX) {
            #pragma unroll
            for (int off = 4; off <= 16; off <<= 1) {
                lm0 = fmaxf(lm0, __shfl_xor_sync(0xFFFFFFFFu, lm0, off));
                lm1 = fmaxf(lm1, __shfl_xor_sync(0xFFFFFFFFu, lm1, off));
            }
            if (g == 0) {
                amax_atomic(&sch[cl], lm0);
                amax_atomic(&sch[cl + 1], lm1);
            }
        }
    }
    if (DO_AMAX) {
        __syncthreads();
        if (tid < 128) amax_atomic(&amax_out[o0 + tid], sch[tid]);
    }
}

// ---------------------------------------------------------------------------
// Final 1x1 conv to 3 channels (warp per pixel)
// ---------------------------------------------------------------------------
__global__ void final_conv(const __nv_bfloat16* __restrict__ InH,
                           const __nv_bfloat16* __restrict__ InL,
                           const float* __restrict__ w,
                           const float* __restrict__ b, float* __restrict__ out) {
    int warp = (blockIdx.x * blockDim.x + threadIdx.x) >> 5;
    int lane = threadIdx.x & 31;
    if (warp >= HWPIX) return;
    const __nv_bfloat16* ph = InH + (size_t)warp * HID;
    const __nv_bfloat16* pl = InL + (size_t)warp * HID;
    float a0 = 0.f, a1 = 0.f, a2 = 0.f;
    #pragma unroll
    for (int t = 0; t < 8; t++) {
        int i = lane + 32 * t;
        float v = __bfloat162float(ph[i]) + __bfloat162float(pl[i]);
        a0 += v * w[i];
        a1 += v * w[HID + i];
        a2 += v * w[2 * HID + i];
    }
    #pragma unroll
    for (int off = 16; off; off >>= 1) {
        a0 += __shfl_xor_sync(0xFFFFFFFFu, a0, off);
        a1 += __shfl_xor_sync(0xFFFFFFFFu, a1, off);
        a2 += __shfl_xor_sync(0xFFFFFFFFu, a2, off);
    }
    if (lane == 0) {
        out[warp]             = a0 + b[0];
        out[HWPIX + warp]     = a1 + b[1];
        out[2 * HWPIX + warp] = a2 + b[2];
    }
}

// ---------------------------------------------------------------------------
// Launch
// ---------------------------------------------------------------------------
extern "C" void kernel_launch(void* const* d_in, const int* in_sizes, int n_in,
                              void* d_out, int out_size) {
    const float* x     = (const float*)d_in[0];
    const float* m     = (const float*)d_in[1];
    const float* z     = (const float*)d_in[2];
    const float* dists = (const float*)d_in[3];
    const float* w1    = (const float*)d_in[4];
    const float* b1    = (const float*)d_in[5];
    const float* wma   = (const float*)d_in[6];
    const float* ml_w  = (const float*)d_in[7];
    const float* ml_wa = (const float*)d_in[8];
    const float* ml_ba = (const float*)d_in[9];
    const float* ml_wb = (const float*)d_in[10];
    const float* ml_bb = (const float*)d_in[11];
    const float* wsig  = (const float*)d_in[12];
    const float* bsig  = (const float*)d_in[13];
    const float* wc    = (const float*)d_in[14];
    const float* bc    = (const float*)d_in[15];
    const float* wz    = (const float*)d_in[16];
    const float* bz    = (const float*)d_in[17];
    const float* c1_w  = (const float*)d_in[18];
    const float* c1_b  = (const float*)d_in[19];
    const float* c2a_w = (const float*)d_in[20];
    const float* c2a_b = (const float*)d_in[21];
    const float* c2b_w = (const float*)d_in[22];
    const float* c3a_w = (const float*)d_in[23];
    const float* c3a_b = (const float*)d_in[24];
    const float* c3b_w = (const float*)d_in[25];
    const float* c4a_w = (const float*)d_in[26];
    const float* c4a_b = (const float*)d_in[27];
    const float* c4b_w = (const float*)d_in[28];
    const float* c4b_b = (const float*)d_in[29];
    const float* c4_w  = (const float*)d_in[30];
    const float* c4_b  = (const float*)d_in[31];
    float* out = (float*)d_out;

    int8_t *xq1, *xq2, *aq1, *aq2, *bq1, *bq2;
    int8_t *w1q1, *w1q2, *wmq1, *wmq2, *wcq1, *wcq2, *cq1, *cq2, *cwq1, *cwq2;
    float *xs, *as, *bsc, *w1s, *wms, *wcs, *wt3f, *cts, *camax;
    __nv_bfloat16 *yah, *yal, *ybh, *ybl, *ych, *ycl, *fth, *ftl;
    float *sig, *zcv, *be;
    cudaGetSymbolAddress((void**)&xq1, d_xq1);
    cudaGetSymbolAddress((void**)&xq2, d_xq2);
    cudaGetSymbolAddress((void**)&xs,  d_xs);
    cudaGetSymbolAddress((void**)&aq1, d_aq1);
    cudaGetSymbolAddress((void**)&aq2, d_aq2);
    cudaGetSymbolAddress((void**)&as,  d_as);
    cudaGetSymbolAddress((void**)&bq1, d_bq1);
    cudaGetSymbolAddress((void**)&bq2, d_bq2);
    cudaGetSymbolAddress((void**)&bsc, d_bsc);
    cudaGetSymbolAddress((void**)&w1q1, d_w1q1);
    cudaGetSymbolAddress((void**)&w1q2, d_w1q2);
    cudaGetSymbolAddress((void**)&w1s,  d_w1s);
    cudaGetSymbolAddress((void**)&wmq1, d_wmq1);
    cudaGetSymbolAddress((void**)&wmq2, d_wmq2);
    cudaGetSymbolAddress((void**)&wms,  d_wms);
    cudaGetSymbolAddress((void**)&wcq1, d_wcq1);
    cudaGetSymbolAddress((void**)&wcq2, d_wcq2);
    cudaGetSymbolAddress((void**)&wcs,  d_wcs);
    cudaGetSymbolAddress((void**)&wt3f, d_wt3f);
    cudaGetSymbolAddress((void**)&cwq1, d_cwq1);
    cudaGetSymbolAddress((void**)&cwq2, d_cwq2);
    cudaGetSymbolAddress((void**)&cts,  d_cts);
    cudaGetSymbolAddress((void**)&camax, d_camax);
    cudaGetSymbolAddress((void**)&cq1, d_cq1);
    cudaGetSymbolAddress((void**)&cq2, d_cq2);
    cudaGetSymbolAddress((void**)&yah, d_yah);
    cudaGetSymbolAddress((void**)&yal, d_yal);
    cudaGetSymbolAddress((void**)&ybh, d_ybh);
    cudaGetSymbolAddress((void**)&ybl, d_ybl);
    cudaGetSymbolAddress((void**)&ych, d_ych);
    cudaGetSymbolAddress((void**)&ycl, d_ycl);
    cudaGetSymbolAddress((void**)&fth, d_feath);
    cudaGetSymbolAddress((void**)&ftl, d_featl);
    cudaGetSymbolAddress((void**)&sig, d_sig);
    cudaGetSymbolAddress((void**)&zcv, d_zc);
    cudaGetSymbolAddress((void**)&be,  d_beta);

    const int TWF = 9 * HID * HID;
    const int SM_L1 = 2 * 3 * (256 * 80) + 3 * (2 * 2 * 64 * 80) + 256;          // 184576
    const int SM_LH = 2 * 4 * (256 * 80) + 3 * (2 * 2 * 64 * 80) + 256;          // 225536
    const int SM_LS = SM_LH + 64 * 8 * 4;                                        // 227584 (sigma slots)
    const int SM_LC = 3 * (2 * 128 * 80 + 2 * 64 * 80);                          // 92160
    const int SMCV  = 3 * (2 * 64 * 80 + 2 * 128 * 80);                          // 92160

    auto L1  = imma_brg<512, 64, 4, 256, KQ1, true, true, false>;
    auto LH  = imma_brg<512, 64, 4, 256, HID, true, true, false>;
    auto LHS = imma_brg<512, 64, 4, 256, HID, true, true, true >;  // fused sigma
    auto CV1  = conv_q<1, COL, true,  false, false, true >;
    auto CVA  = conv_q<9, HID, true,  false, false, true >;
    auto CVB  = conv_q<9, HID, false, true,  true,  true >;
    auto CV4A = conv_q<1, HID, true,  false, false, true >;
    auto CV4B = conv_q<1, HID, true,  true,  false, false>;

    cudaFuncSetAttribute(L1,     cudaFuncAttributeMaxDynamicSharedMemorySize, SM_L1);
    cudaFuncSetAttribute(LH,     cudaFuncAttributeMaxDynamicSharedMemorySize, SM_LH);
    cudaFuncSetAttribute(LHS,    cudaFuncAttributeMaxDynamicSharedMemorySize, SM_LS);
    cudaFuncSetAttribute(lwcomp, cudaFuncAttributeMaxDynamicSharedMemorySize, SM_LC);
    cudaFuncSetAttribute(CV1,  cudaFuncAttributeMaxDynamicSharedMemorySize, SMCV);
    cudaFuncSetAttribute(CVA,  cudaFuncAttributeMaxDynamicSharedMemorySize, SMCV);
    cudaFuncSetAttribute(CVB,  cudaFuncAttributeMaxDynamicSharedMemorySize, SMCV);
    cudaFuncSetAttribute(CV4A, cudaFuncAttributeMaxDynamicSharedMemorySize, SMCV);
    cudaFuncSetAttribute(CV4B, cudaFuncAttributeMaxDynamicSharedMemorySize, SMCV);

    const int GRB = S_TOT / 256;   // 1024 (64 rows x 4 m-tiles per CTA)

    prep_vec<<<448, 256>>>(z, ml_wa, ml_ba, ml_wb, ml_bb, wz, bz);        // 1
    prep_xq<<<S_TOT / 8, 256>>>(x, m);                                    // 2
    prep_w1q<<<HID / 8, 256>>>(w1, wma);                                  // 3
    L1<<<GRB, 512, SM_L1>>>(xq1, xq2, xs, w1q1, w1q2, w1s, b1,
                            aq1, aq2, as, nullptr, HID,
                            nullptr, nullptr, nullptr);                   // 4 <-- ncu
    prep_wmq<<<5 * HID / 8, 256>>>(ml_w);
    prep_wcq<<<COL / 8, 256>>>(wc);
    reset_amax<<<7, 256>>>();

    // --- MLP ---
    LH<<<GRB, 512, SM_LH>>>(aq1, aq2, as, wmq1 + 0 * 65536, wmq2 + 0 * 65536, wms + 0,
                            be + 0,    bq1, bq2, bsc, nullptr, HID,
                            nullptr, nullptr, nullptr);
    LH<<<GRB, 512, SM_LH>>>(bq1, bq2, bsc, wmq1 + 1 * 65536, wmq2 + 1 * 65536, wms + 256,
                            be + 256,  aq1, aq2, as, nullptr, HID,
                            nullptr, nullptr, nullptr);
    LHS<<<GRB, 512, SM_LS>>>(aq1, aq2, as, wmq1 + 2 * 65536, wmq2 + 2 * 65536, wms + 512,
                             be + 512,  bq1, bq2, bsc, nullptr, HID,
                             wsig, bsig, sig);
    LH<<<GRB, 512, SM_LH>>>(bq1, bq2, bsc, wmq1 + 3 * 65536, wmq2 + 3 * 65536, wms + 768,
                            be + 768,  aq1, aq2, as, nullptr, HID,
                            nullptr, nullptr, nullptr);
    LH<<<GRB, 512, SM_LH>>>(aq1, aq2, as, wmq1 + 4 * 65536, wmq2 + 4 * 65536, wms + 1024,
                            be + 1024, bq1, bq2, bsc, nullptr, HID,
                            nullptr, nullptr, nullptr);

    // --- fused wc head + compositing (feat + camax[0]) ---
    lwcomp<<<S_TOT / 128, 256, SM_LC>>>(bq1, bq2, bsc, wcq1, wcq2, wcs, bc,
                                        sig, dists, fth, ftl, camax + 0 * HID);

    // --- CNN weight transposes ---
    prep_twf<<<(TWF + 255) / 256, 256>>>(c2a_w, wt3f + 0 * TWF);
    prep_twf<<<(TWF + 255) / 256, 256>>>(c2b_w, wt3f + 1 * TWF);
    prep_twf<<<(TWF + 255) / 256, 256>>>(c3a_w, wt3f + 2 * TWF);
    prep_twf<<<(TWF + 255) / 256, 256>>>(c3b_w, wt3f + 3 * TWF);

    // --- CNN (int8 IMMA, runtime scale folding; fused quant+wreq) ---
    dim3 gC(2 * HH, 2);
    const int NQ  = (HWPIX * HID + 255) / 256;
    const int NQF = (HWPIX * COL + 255) / 256;

    qa_wr<COL, 1, COL><<<NQF + 32, 256>>>(fth, ftl, camax + 0 * HID, cq1, cq2,
                                          c1_w, cwq1, cwq2, cts, NQF);
    CV1<<<gC, 256, SMCV>>>(cq1, cq2, cwq1, cwq2, cts, c1_b, nullptr, nullptr,
                           nullptr, 0, yah, yal, camax + 1 * HID);

    qa_wr<HID, 9, HID><<<NQ + 32, 256>>>(yah, yal, camax + 1 * HID, cq1, cq2,
                                         wt3f + 0 * TWF, cwq1, cwq2, cts, NQ);
    CVA<<<gC, 256, SMCV>>>(cq1, cq2, cwq1, cwq2, cts, c2a_b, nullptr, nullptr,
                           nullptr, 0, ybh, ybl, camax + 2 * HID);

    qa_wr<HID, 9, HID><<<NQ + 32, 256>>>(ybh, ybl, camax + 2 * HID, cq1, cq2,
                                         wt3f + 1 * TWF, cwq1, cwq2, cts, NQ);
    CVB<<<gC, 256, SMCV>>>(cq1, cq2, cwq1, cwq2, cts, nullptr, yah, yal,
                           zcv, 0, ych, ycl, camax + 3 * HID);

    qa_wr<HID, 9, HID><<<NQ + 32, 256>>>(ych, ycl, camax + 3 * HID, cq1, cq2,
                                         wt3f + 2 * TWF, cwq1, cwq2, cts, NQ);
    CVA<<<gC, 256, SMCV>>>(cq1, cq2, cwq1, cwq2, cts, c3a_b, nullptr, nullptr,
                           nullptr, 0, ybh, ybl, camax + 4 * HID);

    qa_wr<HID, 9, HID><<<NQ + 32, 256>>>(ybh, ybl, camax + 4 * HID, cq1, cq2,
                                         wt3f + 3 * TWF, cwq1, cwq2, cts, NQ);
    CVB<<<gC, 256, SMCV>>>(cq1, cq2, cwq1, cwq2, cts, nullptr, ych, ycl,
                           zcv, 512, yah, yal, camax + 5 * HID);

    qa_wr<HID, 1, HID><<<NQ + 32, 256>>>(yah, yal, camax + 5 * HID, cq1, cq2,
                                         c4a_w, cwq1, cwq2, cts, NQ);
    CV4A<<<gC, 256, SMCV>>>(cq1, cq2, cwq1, cwq2, cts, c4a_b, nullptr, nullptr,
                            nullptr, 0, ybh, ybl, camax + 6 * HID);

    qa_wr<HID, 1, HID><<<NQ + 32, 256>>>(ybh, ybl, camax + 6 * HID, cq1, cq2,
                                         c4b_w, cwq1, cwq2, cts, NQ);
    CV4B<<<gC, 256, SMCV>>>(cq1, cq2, cwq1, cwq2, cts, c4b_b, yah, yal,
                            nullptr, 0, ych, ycl, nullptr);

    final_conv<<<HWPIX / 8, 256>>>(ych, ycl, c4_w, c4_b, out);

    (void)in_sizes; (void)n_in; (void)out_size;
}